// round 6
// baseline (speedup 1.0000x reference)
#include <cuda_runtime.h>
#include <cstdint>

#define BB 128
#define DE 512
#define DL 256
#define G4 2048
#define TST 511

// ---------------- scratch ----------------------------------------------------
__device__ float g_z1[256 * BB * 512];
__device__ float g_z2[512 * BB * 512];
__device__ float g_gx[(size_t)TST * BB * G4];
__device__ float g_h[4][2][32 * 512];
__device__ int   g_flag[128];

// ---------------- helpers ----------------------------------------------------
__device__ __forceinline__ float to_tf32(float x) {
    uint32_t u; asm("cvt.rna.tf32.f32 %0, %1;" : "=r"(u) : "f"(x));
    return __uint_as_float(u);
}
__device__ __forceinline__ float4 to_tf32_4(float4 v) {
    v.x = to_tf32(v.x); v.y = to_tf32(v.y); v.z = to_tf32(v.z); v.w = to_tf32(v.w);
    return v;
}
__device__ __forceinline__ void mma_tf32(float* d, const uint32_t* a, const uint32_t* b) {
    asm volatile(
        "mma.sync.aligned.m16n8k8.row.col.f32.tf32.tf32.f32 "
        "{%0,%1,%2,%3}, {%4,%5,%6,%7}, {%8,%9}, {%0,%1,%2,%3};\n"
        : "+f"(d[0]), "+f"(d[1]), "+f"(d[2]), "+f"(d[3])
        : "r"(a[0]), "r"(a[1]), "r"(a[2]), "r"(a[3]), "r"(b[0]), "r"(b[1]));
}
__device__ __forceinline__ void ldsm4(uint32_t* r, uint32_t addr) {
    asm volatile("ldmatrix.sync.aligned.m8n8.x4.shared.b16 {%0,%1,%2,%3}, [%4];"
        : "=r"(r[0]), "=r"(r[1]), "=r"(r[2]), "=r"(r[3]) : "r"(addr));
}
__device__ __forceinline__ void cp_async16(uint32_t dst, const void* src) {
    asm volatile("cp.async.cg.shared.global [%0], [%1], 16;" :: "r"(dst), "l"(src));
}
__device__ __forceinline__ uint32_t smem_u32(const void* p) {
    uint32_t a;
    asm("{ .reg .u64 t; cvta.to.shared.u64 t, %1; cvt.u32.u64 %0, t; }" : "=r"(a) : "l"(p));
    return a;
}
__device__ __forceinline__ float sigm(float x) { return 1.0f / (1.0f + __expf(-x)); }

// ---------------- upsample convs ---------------------------------------------
__global__ void upsample0(const float* __restrict__ z, const float* __restrict__ w,
                          const float* __restrict__ bias) {
    int c = threadIdx.x, t2 = blockIdx.x, b = blockIdx.y;
    int ch = ((t2 & 1) << 9) + c;
    int l = t2 >> 1;
    int ic = ch >> 2;
    float acc = bias[ch];
#pragma unroll
    for (int k = 0; k < 7; k++) {
        int li = l + k - 3;
        if (li >= 0 && li < 128)
            acc += w[ch * 7 + k] * z[((size_t)li * BB + b) * DL + ic];
    }
    g_z1[((size_t)t2 * BB + b) * 512 + c] = fmaxf(acc, 0.0f);
}

__global__ void upsample1(const float* __restrict__ w, const float* __restrict__ bias) {
    int c = threadIdx.x, t2 = blockIdx.x, b = blockIdx.y;
    int ch = ((t2 & 1) << 9) + c;
    int l = t2 >> 1;
    int ic = ch >> 1;
    float acc = bias[ch];
#pragma unroll
    for (int k = 0; k < 7; k++) {
        int li = l + k - 3;
        if (li >= 0 && li < 256)
            acc += w[ch * 7 + k] * g_z1[((size_t)li * BB + b) * 512 + ic];
    }
    g_z2[((size_t)t2 * BB + b) * 512 + c] = fmaxf(acc, 0.0f);
}

// ---------------- gates_x GEMM (tf32 mma.sync + ldmatrix) --------------------
// CTA tile 128(batch) x 128(n), BK=32, 8 warps (2x4), warp tile 64x32.
// Row-major padded smem (stride 36 ≡ 4 mod 32: LDSM phases conflict-free).
#define GSTR 36
#define GBUF (128 * GSTR)          // floats per tile buffer
#define GBUFB (GBUF * 4)           // bytes
#define GEMM_SMEM (4 * GBUFB)

__global__ void __launch_bounds__(256, 1)
gates_gemm(const float* __restrict__ x, const float* __restrict__ w_ih,
           const float* __restrict__ b_ih, const float* __restrict__ b_hh) {
    extern __shared__ float sm[];
    float* As = sm;                  // [2][128][GSTR]
    float* Bs = sm + 2 * GBUF;       // [2][128][GSTR]
    const uint32_t smb = smem_u32(sm);

    const int t  = blockIdx.y;
    const int n0 = blockIdx.x << 7;
    const int tid = threadIdx.x;
    const int warp = tid >> 5, lane = tid & 31;
    const int gid = lane >> 2, tg = lane & 3;
    const int wm6 = (warp & 1) << 6;     // A row base 0/64
    const int wn5 = (warp >> 1) << 5;    // B n base 0/32/64/96
    const int srow = tid >> 1;
    const int scol = (tid & 1) << 4;

    // LDSM per-lane addresses (bytes)
    const uint32_t a_base = smb +
        (((wm6 + (lane & 15)) * GSTR + ((lane >> 4) << 2)) << 2);
    const uint32_t b_base = smb + 2 * GBUFB +
        (((wn5 + ((lane >> 4) << 3) + (lane & 7)) * GSTR + (((lane >> 3) & 1) << 2)) << 2);

    float acc[4][4][4];
#pragma unroll
    for (int mi = 0; mi < 4; mi++)
#pragma unroll
        for (int ni = 0; ni < 4; ni++)
#pragma unroll
            for (int cc = 0; cc < 4; cc++) acc[mi][ni][cc] = 0.0f;

    float4 a4[4], b4[4];

    auto ldg_tiles = [&](int it) {
        int kglob = it << 5;
        const float* asrc;
        if (kglob < 512)
            asrc = x + ((size_t)t * BB + srow) * DE + kglob + scol;
        else
            asrc = g_z2 + ((size_t)(t + 1) * BB + srow) * 512 + (kglob - 512) + scol;
        const float* bsrc = w_ih + (size_t)(n0 + srow) * 1024 + kglob + scol;
#pragma unroll
        for (int j = 0; j < 4; j++) {
            a4[j] = *reinterpret_cast<const float4*>(asrc + j * 4);
            b4[j] = *reinterpret_cast<const float4*>(bsrc + j * 4);
        }
    };
    auto sts_tiles = [&](int buf) {
        float* ad = As + buf * GBUF + srow * GSTR + scol;
        float* bd = Bs + buf * GBUF + srow * GSTR + scol;
#pragma unroll
        for (int j = 0; j < 4; j++) {
            *reinterpret_cast<float4*>(ad + j * 4) = to_tf32_4(a4[j]);
            *reinterpret_cast<float4*>(bd + j * 4) = to_tf32_4(b4[j]);
        }
    };

    ldg_tiles(0);
    sts_tiles(0);

    for (int it = 0; it < 32; ++it) {
        __syncthreads();
        if (it + 1 < 32) ldg_tiles(it + 1);
        const uint32_t bufo = (it & 1) * GBUFB;
#pragma unroll
        for (int kc = 0; kc < 4; kc++) {
            uint32_t Af[4][4], Bf[2][4];
#pragma unroll
            for (int mi = 0; mi < 4; mi++)
                ldsm4(Af[mi], a_base + bufo + mi * (16 * GSTR * 4) + kc * 32);
#pragma unroll
            for (int pi = 0; pi < 2; pi++)
                ldsm4(Bf[pi], b_base + bufo + pi * (16 * GSTR * 4) + kc * 32);
#pragma unroll
            for (int mi = 0; mi < 4; mi++)
#pragma unroll
                for (int ni = 0; ni < 4; ni++)
                    mma_tf32(acc[mi][ni], Af[mi], &Bf[ni >> 1][(ni & 1) << 1]);
        }
        if (it + 1 < 32) sts_tiles((it + 1) & 1);
    }

    // epilogue
#pragma unroll
    for (int ni = 0; ni < 4; ni++) {
        int cb = n0 + wn5 + ni * 8 + 2 * tg;
        float bb0 = b_ih[cb] + b_hh[cb];
        float bb1 = b_ih[cb + 1] + b_hh[cb + 1];
#pragma unroll
        for (int mi = 0; mi < 4; mi++) {
            int r = wm6 + mi * 16 + gid;
            size_t base = ((size_t)t * BB + r) * G4 + cb;
            *reinterpret_cast<float2*>(g_gx + base) =
                make_float2(acc[mi][ni][0] + bb0, acc[mi][ni][1] + bb1);
            *reinterpret_cast<float2*>(g_gx + base + (size_t)8 * G4) =
                make_float2(acc[mi][ni][2] + bb0, acc[mi][ni][3] + bb1);
        }
    }
}

// ---------------- init -------------------------------------------------------
__global__ void init_state() {
    int idx = blockIdx.x * blockDim.x + threadIdx.x;
    float* hf = &g_h[0][0][0];
    for (int i = idx; i < 4 * 2 * 32 * 512; i += gridDim.x * blockDim.x) hf[i] = 0.0f;
    if (idx < 128) g_flag[idx] = 0;
}

// ---------------- persistent LSTM scan ---------------------------------------
// grid (32 hidden-chunks, 4 batch-groups). CTA: M=32 batch, N=64 gate rows,
// K=512. Row-major smem (stride 516 ≡ 4 mod 32) + ldmatrix; h staged via
// cp.async.cg (producers store tf32-pre-rounded h).
#define SSTR 516
#define WSM_F (64 * SSTR)           // 33024 floats
#define HSM_F (32 * SSTR)           // 16512 floats
#define GS    72
#define SCAN_SMEM ((WSM_F + HSM_F + 32 * GS) * 4)

__global__ void __launch_bounds__(256, 1)
lstm_scan(const float* __restrict__ w_hh, float* __restrict__ out) {
    extern __shared__ float sm[];
    float* wsm = sm;                     // [64][SSTR]
    float* hsm = sm + WSM_F;             // [32][SSTR]
    float* gsm = sm + WSM_F + HSM_F;     // [32][GS]
    const uint32_t smb_w = smem_u32(wsm);
    const uint32_t smb_h = smem_u32(hsm);

    const int hc = blockIdx.x;           // hidden chunk 0..31
    const int gq = blockIdx.y;           // batch group 0..3
    const int tid = threadIdx.x;
    const int warp = tid >> 5, lane = tid & 31;
    const int gid = lane >> 2, tg = lane & 3;
    const int wm = (warp & 1) << 4;      // batch-row base 0/16
    const int wn = (warp >> 1) << 4;     // local col base 0/16/32/48

    // LDSM per-lane addresses
    const uint32_t ha = smb_h +
        (((wm + (lane & 15)) * SSTR + ((lane >> 4) << 2)) << 2);
    const uint32_t wa = smb_w +
        (((wn + ((lane >> 4) << 3) + (lane & 7)) * SSTR + (((lane >> 3) & 1) << 2)) << 2);

    // load w_hh slice -> row-major smem (tf32). rows n = gate*16+u, cols k.
    for (int i = 0; i < 32; i++) {
        int j = tid + i * 256;           // f4 index (8192)
        int row = j >> 7;
        int c4 = j & 127;
        int gate = row >> 4, u = row & 15;
        float4 v = to_tf32_4(*reinterpret_cast<const float4*>(
            w_hh + (size_t)(gate * 512 + hc * 16 + u) * 512 + (c4 << 2)));
        *reinterpret_cast<float4*>(wsm + row * SSTR + (c4 << 2)) = v;
    }
    __syncthreads();

    const int b0 = tid >> 4;             // epilogue: batch row (0..15)
    const int uu = tid & 15;             // hidden unit within chunk
    float c0 = 0.0f, c1 = 0.0f;
    const int myflag = (gq << 5) + hc;

    for (int t = 0; t < TST; t++) {
        const int p = t & 1;

        // prefetch gx (overlaps flag poll)
        size_t gxb0 = ((size_t)t * BB + gq * 32 + b0) * G4 + hc * 16 + uu;
        size_t gxb1 = gxb0 + (size_t)16 * G4;
        float xi0 = __ldcs(g_gx + gxb0),        xi1 = __ldcs(g_gx + gxb1);
        float xf0 = __ldcs(g_gx + gxb0 + 512),  xf1 = __ldcs(g_gx + gxb1 + 512);
        float xg0 = __ldcs(g_gx + gxb0 + 1024), xg1 = __ldcs(g_gx + gxb1 + 1024);
        float xo0 = __ldcs(g_gx + gxb0 + 1536), xo1 = __ldcs(g_gx + gxb1 + 1536);

        // group barrier: 32 parallel flag polls by warp 0
        if (t > 0 && warp == 0) {
            volatile int* fp = &g_flag[(gq << 5) + lane];
            while (__ballot_sync(0xffffffffu, *fp < t)) { }
        }
        __syncthreads();

        // stage h via cp.async.cg (L2-only; data pre-rounded by producers)
        {
            const float* hsrc = g_h[gq][p];
#pragma unroll
            for (int i = 0; i < 16; i++) {
                int j = tid + i * 256;   // 4096 f4
                int row = j >> 7, c4 = j & 127;
                cp_async16(smb_h + (((row * SSTR) + (c4 << 2)) << 2),
                           hsrc + (row << 9) + (c4 << 2));
            }
            asm volatile("cp.async.commit_group;");
            asm volatile("cp.async.wait_group 0;" ::: "memory");
        }
        __syncthreads();

        // gates_h = h @ w_hh_slice^T : 2 LDSM + 2 HMMA per k-chunk
        float acc0[4] = {0.f, 0.f, 0.f, 0.f};
        float acc1[4] = {0.f, 0.f, 0.f, 0.f};
#pragma unroll 8
        for (int kc = 0; kc < 64; kc++) {
            uint32_t Ah[4], Bw[4];
            ldsm4(Ah, ha + kc * 32);
            ldsm4(Bw, wa + kc * 32);
            mma_tf32(acc0, Ah, &Bw[0]);
            mma_tf32(acc1, Ah, &Bw[2]);
        }

        // acc -> gsm [batch][local col]
        {
            int col = wn + 2 * tg;
            gsm[(wm + gid) * GS + col]         = acc0[0];
            gsm[(wm + gid) * GS + col + 1]     = acc0[1];
            gsm[(wm + gid + 8) * GS + col]     = acc0[2];
            gsm[(wm + gid + 8) * GS + col + 1] = acc0[3];
            gsm[(wm + gid) * GS + col + 8]     = acc1[0];
            gsm[(wm + gid) * GS + col + 9]     = acc1[1];
            gsm[(wm + gid + 8) * GS + col + 8] = acc1[2];
            gsm[(wm + gid + 8) * GS + col + 9] = acc1[3];
        }
        __syncthreads();

        // epilogue: two (b,u) pairs per thread
        float* hout = g_h[gq][p ^ 1];
        size_t ob = (size_t)t * (BB * DE) + (size_t)(gq * 32 + b0) * DE + hc * 16 + uu;
        {
            float gi = gsm[b0 * GS + uu]      + xi0;
            float gf = gsm[b0 * GS + 16 + uu] + xf0;
            float gg = gsm[b0 * GS + 32 + uu] + xg0;
            float go = gsm[b0 * GS + 48 + uu] + xo0;
            c0 = sigm(gf) * c0 + sigm(gi) * tanhf(gg);
            float h = sigm(go) * tanhf(c0);
            hout[b0 * 512 + hc * 16 + uu] = to_tf32(h);
            out[ob] = h;
        }
        {
            int b1r = b0 + 16;
            float gi = gsm[b1r * GS + uu]      + xi1;
            float gf = gsm[b1r * GS + 16 + uu] + xf1;
            float gg = gsm[b1r * GS + 32 + uu] + xg1;
            float go = gsm[b1r * GS + 48 + uu] + xo1;
            c1 = sigm(gf) * c1 + sigm(gi) * tanhf(gg);
            float h = sigm(go) * tanhf(c1);
            hout[b1r * 512 + hc * 16 + uu] = to_tf32(h);
            out[ob + (size_t)16 * DE] = h;
        }

        // arrive: make h visible, then publish step count in own slot
        __syncthreads();
        if (tid == 0) {
            __threadfence();
            *((volatile int*)&g_flag[myflag]) = t + 1;
        }
    }
}

// ---------------- launch ------------------------------------------------------
extern "C" void kernel_launch(void* const* d_in, const int* in_sizes, int n_in,
                              void* d_out, int out_size) {
    const float* x       = (const float*)d_in[0];
    const float* z       = (const float*)d_in[1];
    const float* conv0_w = (const float*)d_in[2];
    const float* conv0_b = (const float*)d_in[3];
    const float* conv1_w = (const float*)d_in[4];
    const float* conv1_b = (const float*)d_in[5];
    const float* w_ih    = (const float*)d_in[6];
    const float* w_hh    = (const float*)d_in[7];
    const float* b_ih    = (const float*)d_in[8];
    const float* b_hh    = (const float*)d_in[9];
    float* out = (float*)d_out;

    static bool attr_done = false;
    if (!attr_done) {
        cudaFuncSetAttribute(gates_gemm, cudaFuncAttributeMaxDynamicSharedMemorySize,
                             GEMM_SMEM);
        cudaFuncSetAttribute(lstm_scan, cudaFuncAttributeMaxDynamicSharedMemorySize,
                             SCAN_SMEM);
        attr_done = true;
    }

    init_state<<<64, 512>>>();
    upsample0<<<dim3(256, 128), 512>>>(z, conv0_w, conv0_b);
    upsample1<<<dim3(512, 128), 512>>>(conv1_w, conv1_b);
    gates_gemm<<<dim3(16, TST), 256, GEMM_SMEM>>>(x, w_ih, b_ih, b_hh);
    lstm_scan<<<dim3(32, 4), 256, SCAN_SMEM>>>(w_hh, out);
}

// round 7
// speedup vs baseline: 1.3247x; 1.3247x over previous
#include <cuda_runtime.h>
#include <cuda_fp16.h>
#include <cstdint>

#define BB 128
#define DE 512
#define DL 256
#define G4 2048
#define TST 511

// ---------------- scratch ----------------------------------------------------
__device__ float  g_z1[256 * BB * 512];
__device__ __half g_inp[(size_t)TST * BB * 1024];   // [t][b][k]: k<512 x, else z2[t+1]
__device__ __half g_wih[2048 * 1024];
__device__ float  g_gx[(size_t)TST * BB * G4];
__device__ __half g_h[4][2][32 * 512];
__device__ int    g_flag[128];

// ---------------- helpers ----------------------------------------------------
__device__ __forceinline__ void mma_f16(float* d, const uint32_t* a,
                                        uint32_t b0, uint32_t b1) {
    asm volatile(
        "mma.sync.aligned.m16n8k16.row.col.f32.f16.f16.f32 "
        "{%0,%1,%2,%3}, {%4,%5,%6,%7}, {%8,%9}, {%0,%1,%2,%3};\n"
        : "+f"(d[0]), "+f"(d[1]), "+f"(d[2]), "+f"(d[3])
        : "r"(a[0]), "r"(a[1]), "r"(a[2]), "r"(a[3]), "r"(b0), "r"(b1));
}
__device__ __forceinline__ void ldsm4(uint32_t* r, uint32_t addr) {
    asm volatile("ldmatrix.sync.aligned.m8n8.x4.shared.b16 {%0,%1,%2,%3}, [%4];"
        : "=r"(r[0]), "=r"(r[1]), "=r"(r[2]), "=r"(r[3]) : "r"(addr));
}
__device__ __forceinline__ void cp16(uint32_t dst, const void* src) {
    asm volatile("cp.async.cg.shared.global [%0], [%1], 16;" :: "r"(dst), "l"(src));
}
__device__ __forceinline__ uint32_t smem_u32(const void* p) {
    uint32_t a;
    asm("{ .reg .u64 t; cvta.to.shared.u64 t, %1; cvt.u32.u64 %0, t; }" : "=r"(a) : "l"(p));
    return a;
}
__device__ __forceinline__ uint2 f4_to_h4(float4 v) {
    __half2 lo = __floats2half2_rn(v.x, v.y);
    __half2 hi = __floats2half2_rn(v.z, v.w);
    uint2 r;
    r.x = *reinterpret_cast<uint32_t*>(&lo);
    r.y = *reinterpret_cast<uint32_t*>(&hi);
    return r;
}
__device__ __forceinline__ float sigm(float x) { return 1.0f / (1.0f + __expf(-x)); }

// ---------------- upsample convs ---------------------------------------------
__global__ void upsample0(const float* __restrict__ z, const float* __restrict__ w,
                          const float* __restrict__ bias) {
    int c = threadIdx.x, t2 = blockIdx.x, b = blockIdx.y;
    int ch = ((t2 & 1) << 9) + c;
    int l = t2 >> 1;
    int ic = ch >> 2;
    float acc = bias[ch];
#pragma unroll
    for (int k = 0; k < 7; k++) {
        int li = l + k - 3;
        if (li >= 0 && li < 128)
            acc += w[ch * 7 + k] * z[((size_t)li * BB + b) * DL + ic];
    }
    g_z1[((size_t)t2 * BB + b) * 512 + c] = fmaxf(acc, 0.0f);
}

// writes z2 (fp16) straight into g_inp at [t2-1][b][512+c]
__global__ void upsample1(const float* __restrict__ w, const float* __restrict__ bias) {
    int c = threadIdx.x, t2 = blockIdx.x, b = blockIdx.y;
    int ch = ((t2 & 1) << 9) + c;
    int l = t2 >> 1;
    int ic = ch >> 1;
    float acc = bias[ch];
#pragma unroll
    for (int k = 0; k < 7; k++) {
        int li = l + k - 3;
        if (li >= 0 && li < 256)
            acc += w[ch * 7 + k] * g_z1[((size_t)li * BB + b) * 512 + ic];
    }
    if (t2 >= 1)
        g_inp[((size_t)(t2 - 1) * BB + b) * 1024 + 512 + c] =
            __float2half_rn(fmaxf(acc, 0.0f));
}

// ---------------- pack kernels ------------------------------------------------
__global__ void pack_x(const float* __restrict__ x) {
    int t = blockIdx.x, b = blockIdx.y;
    int c4 = threadIdx.x << 2;
    float4 v = *reinterpret_cast<const float4*>(x + ((size_t)t * BB + b) * DE + c4);
    *reinterpret_cast<uint2*>(&g_inp[((size_t)t * BB + b) * 1024 + c4]) = f4_to_h4(v);
}
__global__ void pack_w(const float* __restrict__ w_ih) {
    int row = blockIdx.x;
    int c4 = threadIdx.x << 2;
    float4 v = *reinterpret_cast<const float4*>(w_ih + (size_t)row * 1024 + c4);
    *reinterpret_cast<uint2*>(&g_wih[(size_t)row * 1024 + c4]) = f4_to_h4(v);
}

// ---------------- gates_x GEMM (fp16 m16n8k16 + cp.async + ldmatrix) ---------
// CTA: 256 rows (2 timesteps x 128 batch) x 128 n, BK=32. 8 warps, warp 64x64.
#define HSTR 40                       // halves per row (80B, 16B-aligned, ldsm-clean)
#define ABYTES (256 * HSTR * 2)       // 20480
#define BUFB   (ABYTES + 128 * HSTR * 2)  // 30720
#define GEMM_SMEM (2 * BUFB)          // 61440

__global__ void __launch_bounds__(256, 1)
gates_gemm(const float* __restrict__ b_ih, const float* __restrict__ b_hh) {
    extern __shared__ char smc[];
    const uint32_t smb = smem_u32(smc);

    const int n0 = blockIdx.x << 7;
    const int t0 = blockIdx.y << 1;
    const int tid = threadIdx.x;
    const int warp = tid >> 5, lane = tid & 31;
    const int gid = lane >> 2, tg = lane & 3;
    const int wm = (warp >> 1) << 6;   // row base 0/64/128/192
    const int wn = (warp & 1) << 6;    // n base 0/64

    // ldsm lane addressing (bytes): row = tilebase + (lane&15), colgrp = (lane>>4)*16B
    const uint32_t lrow = (lane & 15);
    const uint32_t lcol = (lane >> 4) << 4;
    const uint32_t a_base = smb + (wm + lrow) * (HSTR * 2) + lcol;
    const uint32_t b_base = smb + ABYTES + (wn + lrow) * (HSTR * 2) + lcol;

    float acc[4][8][4];
#pragma unroll
    for (int mi = 0; mi < 4; mi++)
#pragma unroll
        for (int ni = 0; ni < 8; ni++)
#pragma unroll
            for (int cc = 0; cc < 4; cc++) acc[mi][ni][cc] = 0.0f;

    // staging (cp.async)
    const int ar = tid;                         // A row 0..255
    int atr = t0 + (ar >> 7); if (atr > TST - 1) atr = TST - 1;
    const __half* asrc0 = g_inp + ((size_t)atr * BB + (ar & 127)) * 1024;
    const uint32_t adst0 = smb + ar * (HSTR * 2);
    const int brow = tid >> 1, bseg = tid & 1;
    const __half* bsrc0 = g_wih + (size_t)(n0 + brow) * 1024 + bseg * 16;
    const uint32_t bdst0 = smb + ABYTES + brow * (HSTR * 2) + bseg * 32;

    auto issue = [&](int it) {
        const uint32_t bo = (it & 1) * BUFB;
        const int kb = it << 5;
        cp16(adst0 + bo,      asrc0 + kb);
        cp16(adst0 + bo + 16, asrc0 + kb + 8);
        cp16(adst0 + bo + 32, asrc0 + kb + 16);
        cp16(adst0 + bo + 48, asrc0 + kb + 24);
        cp16(bdst0 + bo,      bsrc0 + kb);
        cp16(bdst0 + bo + 16, bsrc0 + kb + 8);
        asm volatile("cp.async.commit_group;");
    };

    issue(0);

#pragma unroll 1
    for (int it = 0; it < 32; ++it) {
        asm volatile("cp.async.wait_group 0;" ::: "memory");
        __syncthreads();
        if (it + 1 < 32) issue(it + 1);
        const uint32_t bo = (it & 1) * BUFB;
#pragma unroll
        for (int kc = 0; kc < 2; kc++) {
            uint32_t Af[4][4], Bf[4][4];
#pragma unroll
            for (int mi = 0; mi < 4; mi++)
                ldsm4(Af[mi], a_base + bo + mi * (16 * HSTR * 2) + kc * 32);
#pragma unroll
            for (int p = 0; p < 4; p++)
                ldsm4(Bf[p], b_base + bo + p * (16 * HSTR * 2) + kc * 32);
#pragma unroll
            for (int mi = 0; mi < 4; mi++)
#pragma unroll
                for (int p = 0; p < 4; p++) {
                    mma_f16(acc[mi][2 * p],     Af[mi], Bf[p][0], Bf[p][2]);
                    mma_f16(acc[mi][2 * p + 1], Af[mi], Bf[p][1], Bf[p][3]);
                }
        }
        __syncthreads();
    }

    // epilogue
#pragma unroll
    for (int mi = 0; mi < 4; mi++) {
        int rb = wm + mi * 16;
        int tr = t0 + (rb >> 7);
        if (tr >= TST) continue;
        int r = rb + gid;
#pragma unroll
        for (int ni = 0; ni < 8; ni++) {
            int cb = n0 + wn + ni * 8 + 2 * tg;
            float bb0 = b_ih[cb] + b_hh[cb];
            float bb1 = b_ih[cb + 1] + b_hh[cb + 1];
            size_t base = ((size_t)tr * BB + (r & 127)) * G4 + cb;
            *reinterpret_cast<float2*>(g_gx + base) =
                make_float2(acc[mi][ni][0] + bb0, acc[mi][ni][1] + bb1);
            *reinterpret_cast<float2*>(g_gx + base + (size_t)8 * G4) =
                make_float2(acc[mi][ni][2] + bb0, acc[mi][ni][3] + bb1);
        }
    }
}

// ---------------- init -------------------------------------------------------
__global__ void init_state() {
    int idx = blockIdx.x * blockDim.x + threadIdx.x;
    uint32_t* hf = reinterpret_cast<uint32_t*>(&g_h[0][0][0]);
    for (int i = idx; i < 4 * 2 * 32 * 256; i += gridDim.x * blockDim.x) hf[i] = 0u;
    if (idx < 128) g_flag[idx] = 0;
}

// ---------------- persistent LSTM scan (fp16) --------------------------------
// grid (32 hidden-chunks, 4 batch-groups). CTA: M=32 batch, N=64 gate rows, K=512.
#define WST 520                          // halves per weight/h row (1040B)
#define WSM_B (64 * WST * 2)             // 66560
#define HSM_B (32 * WST * 2)             // 33280
#define GS 72
#define SCAN_SMEM (WSM_B + HSM_B + 32 * GS * 4)

__global__ void __launch_bounds__(256, 1)
lstm_scan(const float* __restrict__ w_hh, float* __restrict__ out) {
    extern __shared__ char smc[];
    __half* wsm = reinterpret_cast<__half*>(smc);
    __half* hsm = reinterpret_cast<__half*>(smc + WSM_B);
    float*  gsm = reinterpret_cast<float*>(smc + WSM_B + HSM_B);
    const uint32_t smb_w = smem_u32(wsm);
    const uint32_t smb_h = smem_u32(hsm);

    const int hc = blockIdx.x;
    const int gq = blockIdx.y;
    const int tid = threadIdx.x;
    const int warp = tid >> 5, lane = tid & 31;
    const int gid = lane >> 2, tg = lane & 3;
    const int wm = (warp & 1) << 4;       // batch base 0/16
    const int wn = (warp >> 1) << 4;      // gate-row base 0/16/32/48

    const uint32_t lrow = (lane & 15);
    const uint32_t lcol = (lane >> 4) << 4;
    const uint32_t ha = smb_h + (wm + lrow) * (WST * 2) + lcol;
    const uint32_t wa = smb_w + (wn + lrow) * (WST * 2) + lcol;

    // load w_hh slice (fp32 -> fp16 smem). rows n = gate*16 + u, cols k (512).
    for (int i = 0; i < 32; i++) {
        int j = tid + i * 256;            // float4 index, 8192 total
        int row = j >> 7;
        int c4 = (j & 127) << 2;
        int gate = row >> 4, u = row & 15;
        float4 v = *reinterpret_cast<const float4*>(
            w_hh + (size_t)(gate * 512 + hc * 16 + u) * 512 + c4);
        *reinterpret_cast<uint2*>(&wsm[row * WST + c4]) = f4_to_h4(v);
    }
    __syncthreads();

    const int b0 = tid >> 4;
    const int uu = tid & 15;
    float c0 = 0.0f, c1 = 0.0f;
    const int myflag = (gq << 5) + hc;

    for (int t = 0; t < TST; t++) {
        const int p = t & 1;

        // prefetch gx (fp32)
        size_t gxb0 = ((size_t)t * BB + gq * 32 + b0) * G4 + hc * 16 + uu;
        size_t gxb1 = gxb0 + (size_t)16 * G4;
        float xi0 = __ldcs(g_gx + gxb0),        xi1 = __ldcs(g_gx + gxb1);
        float xf0 = __ldcs(g_gx + gxb0 + 512),  xf1 = __ldcs(g_gx + gxb1 + 512);
        float xg0 = __ldcs(g_gx + gxb0 + 1024), xg1 = __ldcs(g_gx + gxb1 + 1024);
        float xo0 = __ldcs(g_gx + gxb0 + 1536), xo1 = __ldcs(g_gx + gxb1 + 1536);

        // group barrier: warp0 polls 32 flags with backoff
        if (t > 0 && warp == 0) {
            volatile int* fp = &g_flag[(gq << 5) + lane];
            while (true) {
                int v = *fp;
                if (__all_sync(0xffffffffu, v >= t)) break;
                __nanosleep(64);
            }
        }
        __syncthreads();

        // stage h (fp16, 32KB) via cp.async.cg
        {
            const __half* hsrc = g_h[gq][p];
#pragma unroll
            for (int i = 0; i < 8; i++) {
                int j = tid + i * 256;    // 16B-chunk index, 2048 total
                int row = j >> 6, c8 = (j & 63) << 3;
                cp16(smb_h + row * (WST * 2) + c8 * 2, hsrc + (row << 9) + c8);
            }
            asm volatile("cp.async.commit_group;");
            asm volatile("cp.async.wait_group 0;" ::: "memory");
        }
        __syncthreads();

        // gates_h = h @ w_slice^T
        float acc0[4] = {0.f, 0.f, 0.f, 0.f};
        float acc1[4] = {0.f, 0.f, 0.f, 0.f};
#pragma unroll 8
        for (int kc = 0; kc < 32; kc++) {
            uint32_t Ah[4], Bw[4];
            ldsm4(Ah, ha + kc * 32);
            ldsm4(Bw, wa + kc * 32);
            mma_f16(acc0, Ah, Bw[0], Bw[2]);
            mma_f16(acc1, Ah, Bw[1], Bw[3]);
        }

        {
            int col = wn + 2 * tg;
            gsm[(wm + gid) * GS + col]         = acc0[0];
            gsm[(wm + gid) * GS + col + 1]     = acc0[1];
            gsm[(wm + gid + 8) * GS + col]     = acc0[2];
            gsm[(wm + gid + 8) * GS + col + 1] = acc0[3];
            gsm[(wm + gid) * GS + col + 8]     = acc1[0];
            gsm[(wm + gid) * GS + col + 9]     = acc1[1];
            gsm[(wm + gid + 8) * GS + col + 8] = acc1[2];
            gsm[(wm + gid + 8) * GS + col + 9] = acc1[3];
        }
        __syncthreads();

        // epilogue: two (b,u) pairs; publish h + flag BEFORE fp32 out stores
        __half* hout = g_h[gq][p ^ 1];
        float h0, h1;
        {
            float gi = gsm[b0 * GS + uu]      + xi0;
            float gf = gsm[b0 * GS + 16 + uu] + xf0;
            float gg = gsm[b0 * GS + 32 + uu] + xg0;
            float go = gsm[b0 * GS + 48 + uu] + xo0;
            c0 = sigm(gf) * c0 + sigm(gi) * tanhf(gg);
            h0 = sigm(go) * tanhf(c0);
            hout[b0 * 512 + hc * 16 + uu] = __float2half_rn(h0);
        }
        {
            int b1r = b0 + 16;
            float gi = gsm[b1r * GS + uu]      + xi1;
            float gf = gsm[b1r * GS + 16 + uu] + xf1;
            float gg = gsm[b1r * GS + 32 + uu] + xg1;
            float go = gsm[b1r * GS + 48 + uu] + xo1;
            c1 = sigm(gf) * c1 + sigm(gi) * tanhf(gg);
            h1 = sigm(go) * tanhf(c1);
            hout[(b0 + 16) * 512 + hc * 16 + uu] = __float2half_rn(h1);
        }
        __syncthreads();
        if (tid == 0) {
            __threadfence();
            *((volatile int*)&g_flag[myflag]) = t + 1;
        }
        // out stores off the critical path
        size_t ob = (size_t)t * (BB * DE) + (size_t)(gq * 32 + b0) * DE + hc * 16 + uu;
        out[ob] = h0;
        out[ob + (size_t)16 * DE] = h1;
    }
}

// ---------------- launch ------------------------------------------------------
extern "C" void kernel_launch(void* const* d_in, const int* in_sizes, int n_in,
                              void* d_out, int out_size) {
    const float* x       = (const float*)d_in[0];
    const float* z       = (const float*)d_in[1];
    const float* conv0_w = (const float*)d_in[2];
    const float* conv0_b = (const float*)d_in[3];
    const float* conv1_w = (const float*)d_in[4];
    const float* conv1_b = (const float*)d_in[5];
    const float* w_ih    = (const float*)d_in[6];
    const float* w_hh    = (const float*)d_in[7];
    const float* b_ih    = (const float*)d_in[8];
    const float* b_hh    = (const float*)d_in[9];
    float* out = (float*)d_out;

    static bool attr_done = false;
    if (!attr_done) {
        cudaFuncSetAttribute(gates_gemm, cudaFuncAttributeMaxDynamicSharedMemorySize,
                             GEMM_SMEM);
        cudaFuncSetAttribute(lstm_scan, cudaFuncAttributeMaxDynamicSharedMemorySize,
                             SCAN_SMEM);
        attr_done = true;
    }

    init_state<<<64, 512>>>();
    upsample0<<<dim3(256, 128), 512>>>(z, conv0_w, conv0_b);
    upsample1<<<dim3(512, 128), 512>>>(conv1_w, conv1_b);
    pack_x<<<dim3(TST, BB), 128>>>(x);
    pack_w<<<2048, 256>>>(w_ih);
    gates_gemm<<<dim3(16, 256), 256, GEMM_SMEM>>>(b_ih, b_hh);
    lstm_scan<<<dim3(32, 4), 256, SCAN_SMEM>>>(w_hh, out);
}

// round 8
// speedup vs baseline: 1.4056x; 1.0611x over previous
#include <cuda_runtime.h>
#include <cuda_fp16.h>
#include <cstdint>

#define BB 128
#define DE 512
#define DL 256
#define G4 2048
#define TST 511

// ---------------- scratch ----------------------------------------------------
__device__ float  g_z1[256 * BB * 512];
__device__ __half g_inp[(size_t)TST * BB * 1024];   // [t][b][k]: k<512 x, else z2[t+1]
__device__ __half g_wih[2048 * 1024];
__device__ float  g_gx[(size_t)TST * BB * G4];
__device__ __half g_h[4][2][32 * 512];
__device__ int    g_flag[128];

// ---------------- helpers ----------------------------------------------------
__device__ __forceinline__ void mma_f16(float* d, const uint32_t* a,
                                        uint32_t b0, uint32_t b1) {
    asm volatile(
        "mma.sync.aligned.m16n8k16.row.col.f32.f16.f16.f32 "
        "{%0,%1,%2,%3}, {%4,%5,%6,%7}, {%8,%9}, {%0,%1,%2,%3};\n"
        : "+f"(d[0]), "+f"(d[1]), "+f"(d[2]), "+f"(d[3])
        : "r"(a[0]), "r"(a[1]), "r"(a[2]), "r"(a[3]), "r"(b0), "r"(b1));
}
__device__ __forceinline__ void ldsm4(uint32_t* r, uint32_t addr) {
    asm volatile("ldmatrix.sync.aligned.m8n8.x4.shared.b16 {%0,%1,%2,%3}, [%4];"
        : "=r"(r[0]), "=r"(r[1]), "=r"(r[2]), "=r"(r[3]) : "r"(addr));
}
__device__ __forceinline__ void cp16(uint32_t dst, const void* src) {
    asm volatile("cp.async.cg.shared.global [%0], [%1], 16;" :: "r"(dst), "l"(src));
}
__device__ __forceinline__ uint32_t smem_u32(const void* p) {
    uint32_t a;
    asm("{ .reg .u64 t; cvta.to.shared.u64 t, %1; cvt.u32.u64 %0, t; }" : "=r"(a) : "l"(p));
    return a;
}
__device__ __forceinline__ uint2 f4_to_h4(float4 v) {
    __half2 lo = __floats2half2_rn(v.x, v.y);
    __half2 hi = __floats2half2_rn(v.z, v.w);
    uint2 r;
    r.x = *reinterpret_cast<uint32_t*>(&lo);
    r.y = *reinterpret_cast<uint32_t*>(&hi);
    return r;
}
// fast transcendentals (MUFU tanh, sm_75+); |err| ~2^-11, fine for 1e-3 tol
__device__ __forceinline__ float tanh_fast(float x) {
    float r; asm("tanh.approx.f32 %0, %1;" : "=f"(r) : "f"(x)); return r;
}
__device__ __forceinline__ float sigm(float x) {
    return fmaf(tanh_fast(0.5f * x), 0.5f, 0.5f);
}

// ---------------- upsample convs ---------------------------------------------
__global__ void upsample0(const float* __restrict__ z, const float* __restrict__ w,
                          const float* __restrict__ bias) {
    int c = threadIdx.x, t2 = blockIdx.x, b = blockIdx.y;
    int ch = ((t2 & 1) << 9) + c;
    int l = t2 >> 1;
    int ic = ch >> 2;
    float acc = bias[ch];
#pragma unroll
    for (int k = 0; k < 7; k++) {
        int li = l + k - 3;
        if (li >= 0 && li < 128)
            acc += w[ch * 7 + k] * z[((size_t)li * BB + b) * DL + ic];
    }
    g_z1[((size_t)t2 * BB + b) * 512 + c] = fmaxf(acc, 0.0f);
}

// writes z2 (fp16) straight into g_inp at [t2-1][b][512+c]
__global__ void upsample1(const float* __restrict__ w, const float* __restrict__ bias) {
    int c = threadIdx.x, t2 = blockIdx.x, b = blockIdx.y;
    int ch = ((t2 & 1) << 9) + c;
    int l = t2 >> 1;
    int ic = ch >> 1;
    float acc = bias[ch];
#pragma unroll
    for (int k = 0; k < 7; k++) {
        int li = l + k - 3;
        if (li >= 0 && li < 256)
            acc += w[ch * 7 + k] * g_z1[((size_t)li * BB + b) * 512 + ic];
    }
    if (t2 >= 1)
        g_inp[((size_t)(t2 - 1) * BB + b) * 1024 + 512 + c] =
            __float2half_rn(fmaxf(acc, 0.0f));
}

// ---------------- pack kernels ------------------------------------------------
__global__ void pack_x(const float* __restrict__ x) {
    int t = blockIdx.x, b = blockIdx.y;
    int c4 = threadIdx.x << 2;
    float4 v = *reinterpret_cast<const float4*>(x + ((size_t)t * BB + b) * DE + c4);
    *reinterpret_cast<uint2*>(&g_inp[((size_t)t * BB + b) * 1024 + c4]) = f4_to_h4(v);
}
__global__ void pack_w(const float* __restrict__ w_ih) {
    int row = blockIdx.x;
    int c4 = threadIdx.x << 2;
    float4 v = *reinterpret_cast<const float4*>(w_ih + (size_t)row * 1024 + c4);
    *reinterpret_cast<uint2*>(&g_wih[(size_t)row * 1024 + c4]) = f4_to_h4(v);
}

// ---------------- gates_x GEMM (fp16 m16n8k16, 3-stage cp.async) -------------
// CTA: 256 rows (2 timesteps x 128 batch) x 128 n, BK=32. 8 warps, warp 64x64.
#define HSTR 40                       // halves per row (80B, 16B-aligned, ldsm-clean)
#define ABYTES (256 * HSTR * 2)       // 20480
#define BUFB   (ABYTES + 128 * HSTR * 2)  // 30720
#define GEMM_SMEM (3 * BUFB)          // 92160

__global__ void __launch_bounds__(256, 1)
gates_gemm(const float* __restrict__ b_ih, const float* __restrict__ b_hh) {
    extern __shared__ char smc[];
    const uint32_t smb = smem_u32(smc);

    const int n0 = blockIdx.x << 7;
    const int t0 = blockIdx.y << 1;
    const int tid = threadIdx.x;
    const int warp = tid >> 5, lane = tid & 31;
    const int gid = lane >> 2, tg = lane & 3;
    const int wm = (warp >> 1) << 6;   // row base 0/64/128/192
    const int wn = (warp & 1) << 6;    // n base 0/64

    const uint32_t lrow = (lane & 15);
    const uint32_t lcol = (lane >> 4) << 4;
    const uint32_t a_base = smb + (wm + lrow) * (HSTR * 2) + lcol;
    const uint32_t b_base = smb + ABYTES + (wn + lrow) * (HSTR * 2) + lcol;

    float acc[4][8][4];
#pragma unroll
    for (int mi = 0; mi < 4; mi++)
#pragma unroll
        for (int ni = 0; ni < 8; ni++)
#pragma unroll
            for (int cc = 0; cc < 4; cc++) acc[mi][ni][cc] = 0.0f;

    const int ar = tid;                         // A row 0..255
    int atr = t0 + (ar >> 7); if (atr > TST - 1) atr = TST - 1;
    const __half* asrc0 = g_inp + ((size_t)atr * BB + (ar & 127)) * 1024;
    const uint32_t adst0 = smb + ar * (HSTR * 2);
    const int brow = tid >> 1, bseg = tid & 1;
    const __half* bsrc0 = g_wih + (size_t)(n0 + brow) * 1024 + bseg * 16;
    const uint32_t bdst0 = smb + ABYTES + brow * (HSTR * 2) + bseg * 32;

    auto issue = [&](int it) {
        const uint32_t bo = (it % 3) * BUFB;
        const int kb = it << 5;
        cp16(adst0 + bo,      asrc0 + kb);
        cp16(adst0 + bo + 16, asrc0 + kb + 8);
        cp16(adst0 + bo + 32, asrc0 + kb + 16);
        cp16(adst0 + bo + 48, asrc0 + kb + 24);
        cp16(bdst0 + bo,      bsrc0 + kb);
        cp16(bdst0 + bo + 16, bsrc0 + kb + 8);
        asm volatile("cp.async.commit_group;");
    };

    issue(0);
    issue(1);

#pragma unroll 1
    for (int it = 0; it < 32; ++it) {
        if (it < 30) {
            asm volatile("cp.async.wait_group 1;" ::: "memory");
        } else {
            asm volatile("cp.async.wait_group 0;" ::: "memory");
        }
        __syncthreads();
        if (it + 2 < 32) issue(it + 2);
        const uint32_t bo = (it % 3) * BUFB;
#pragma unroll
        for (int kc = 0; kc < 2; kc++) {
            uint32_t Af[4][4], Bf[4][4];
#pragma unroll
            for (int mi = 0; mi < 4; mi++)
                ldsm4(Af[mi], a_base + bo + mi * (16 * HSTR * 2) + kc * 32);
#pragma unroll
            for (int p = 0; p < 4; p++)
                ldsm4(Bf[p], b_base + bo + p * (16 * HSTR * 2) + kc * 32);
#pragma unroll
            for (int mi = 0; mi < 4; mi++)
#pragma unroll
                for (int p = 0; p < 4; p++) {
                    mma_f16(acc[mi][2 * p],     Af[mi], Bf[p][0], Bf[p][2]);
                    mma_f16(acc[mi][2 * p + 1], Af[mi], Bf[p][1], Bf[p][3]);
                }
        }
    }

    // epilogue
#pragma unroll
    for (int mi = 0; mi < 4; mi++) {
        int rb = wm + mi * 16;
        int tr = t0 + (rb >> 7);
        if (tr >= TST) continue;
        int r = rb + gid;
#pragma unroll
        for (int ni = 0; ni < 8; ni++) {
            int cb = n0 + wn + ni * 8 + 2 * tg;
            float bb0 = b_ih[cb] + b_hh[cb];
            float bb1 = b_ih[cb + 1] + b_hh[cb + 1];
            size_t base = ((size_t)tr * BB + (r & 127)) * G4 + cb;
            *reinterpret_cast<float2*>(g_gx + base) =
                make_float2(acc[mi][ni][0] + bb0, acc[mi][ni][1] + bb1);
            *reinterpret_cast<float2*>(g_gx + base + (size_t)8 * G4) =
                make_float2(acc[mi][ni][2] + bb0, acc[mi][ni][3] + bb1);
        }
    }
}

// ---------------- init -------------------------------------------------------
__global__ void init_state() {
    int idx = blockIdx.x * blockDim.x + threadIdx.x;
    uint32_t* hf = reinterpret_cast<uint32_t*>(&g_h[0][0][0]);
    for (int i = idx; i < 4 * 2 * 32 * 256; i += gridDim.x * blockDim.x) hf[i] = 0u;
    if (idx < 128) g_flag[idx] = 0;
}

// ---------------- persistent LSTM scan (fp16) --------------------------------
// grid (32 hidden-chunks, 4 batch-groups). CTA: M=32 batch, N=64 gate rows, K=512.
#define WST 520                          // halves per weight/h row (1040B)
#define WSM_B (64 * WST * 2)             // 66560
#define HSM_B (32 * WST * 2)             // 33280
#define GS 72
#define SCAN_SMEM (WSM_B + HSM_B + 32 * GS * 4)

__global__ void __launch_bounds__(256, 1)
lstm_scan(const float* __restrict__ w_hh, float* __restrict__ out) {
    extern __shared__ char smc[];
    __half* wsm = reinterpret_cast<__half*>(smc);
    __half* hsm = reinterpret_cast<__half*>(smc + WSM_B);
    float*  gsm = reinterpret_cast<float*>(smc + WSM_B + HSM_B);
    const uint32_t smb_w = smem_u32(wsm);
    const uint32_t smb_h = smem_u32(hsm);

    const int hc = blockIdx.x;
    const int gq = blockIdx.y;
    const int tid = threadIdx.x;
    const int warp = tid >> 5, lane = tid & 31;
    const int gid = lane >> 2, tg = lane & 3;
    const int wm = (warp & 1) << 4;       // batch base 0/16
    const int wn = (warp >> 1) << 4;      // gate-row base 0/16/32/48

    const uint32_t lrow = (lane & 15);
    const uint32_t lcol = (lane >> 4) << 4;
    const uint32_t ha = smb_h + (wm + lrow) * (WST * 2) + lcol;
    const uint32_t wa = smb_w + (wn + lrow) * (WST * 2) + lcol;

    // load w_hh slice (fp32 -> fp16 smem). rows n = gate*16 + u, cols k (512).
    for (int i = 0; i < 32; i++) {
        int j = tid + i * 256;            // float4 index, 8192 total
        int row = j >> 7;
        int c4 = (j & 127) << 2;
        int gate = row >> 4, u = row & 15;
        float4 v = *reinterpret_cast<const float4*>(
            w_hh + (size_t)(gate * 512 + hc * 16 + u) * 512 + c4);
        *reinterpret_cast<uint2*>(&wsm[row * WST + c4]) = f4_to_h4(v);
    }
    __syncthreads();

    const int b0 = tid >> 4;
    const int uu = tid & 15;
    float c0 = 0.0f, c1 = 0.0f;
    const int myflag = (gq << 5) + hc;

    for (int t = 0; t < TST; t++) {
        const int p = t & 1;

        // prefetch gx (fp32)
        size_t gxb0 = ((size_t)t * BB + gq * 32 + b0) * G4 + hc * 16 + uu;
        size_t gxb1 = gxb0 + (size_t)16 * G4;
        float xi0 = __ldcs(g_gx + gxb0),        xi1 = __ldcs(g_gx + gxb1);
        float xf0 = __ldcs(g_gx + gxb0 + 512),  xf1 = __ldcs(g_gx + gxb1 + 512);
        float xg0 = __ldcs(g_gx + gxb0 + 1024), xg1 = __ldcs(g_gx + gxb1 + 1024);
        float xo0 = __ldcs(g_gx + gxb0 + 1536), xo1 = __ldcs(g_gx + gxb1 + 1536);

        // group barrier: warp0 hard-polls 32 flags
        if (t > 0 && warp == 0) {
            volatile int* fp = &g_flag[(gq << 5) + lane];
            while (!__all_sync(0xffffffffu, *fp >= t)) { }
        }
        __syncthreads();

        // stage h (fp16, 32KB) via cp.async.cg
        {
            const __half* hsrc = g_h[gq][p];
#pragma unroll
            for (int i = 0; i < 8; i++) {
                int j = tid + i * 256;    // 16B-chunk index, 2048 total
                int row = j >> 6, c8 = (j & 63) << 3;
                cp16(smb_h + row * (WST * 2) + c8 * 2, hsrc + (row << 9) + c8);
            }
            asm volatile("cp.async.commit_group;");
            asm volatile("cp.async.wait_group 0;" ::: "memory");
        }
        __syncthreads();

        // gates_h = h @ w_slice^T
        float acc0[4] = {0.f, 0.f, 0.f, 0.f};
        float acc1[4] = {0.f, 0.f, 0.f, 0.f};
#pragma unroll 8
        for (int kc = 0; kc < 32; kc++) {
            uint32_t Ah[4], Bw[4];
            ldsm4(Ah, ha + kc * 32);
            ldsm4(Bw, wa + kc * 32);
            mma_f16(acc0, Ah, Bw[0], Bw[2]);
            mma_f16(acc1, Ah, Bw[1], Bw[3]);
        }

        {
            int col = wn + 2 * tg;
            gsm[(wm + gid) * GS + col]         = acc0[0];
            gsm[(wm + gid) * GS + col + 1]     = acc0[1];
            gsm[(wm + gid + 8) * GS + col]     = acc0[2];
            gsm[(wm + gid + 8) * GS + col + 1] = acc0[3];
            gsm[(wm + gid) * GS + col + 8]     = acc1[0];
            gsm[(wm + gid) * GS + col + 9]     = acc1[1];
            gsm[(wm + gid + 8) * GS + col + 8] = acc1[2];
            gsm[(wm + gid + 8) * GS + col + 9] = acc1[3];
        }
        __syncthreads();

        // epilogue: two (b,u) pairs; publish h + flag BEFORE fp32 out stores
        __half* hout = g_h[gq][p ^ 1];
        float h0, h1;
        {
            float gi = gsm[b0 * GS + uu]      + xi0;
            float gf = gsm[b0 * GS + 16 + uu] + xf0;
            float gg = gsm[b0 * GS + 32 + uu] + xg0;
            float go = gsm[b0 * GS + 48 + uu] + xo0;
            c0 = sigm(gf) * c0 + sigm(gi) * tanh_fast(gg);
            h0 = sigm(go) * tanh_fast(c0);
            hout[b0 * 512 + hc * 16 + uu] = __float2half_rn(h0);
        }
        {
            int b1r = b0 + 16;
            float gi = gsm[b1r * GS + uu]      + xi1;
            float gf = gsm[b1r * GS + 16 + uu] + xf1;
            float gg = gsm[b1r * GS + 32 + uu] + xg1;
            float go = gsm[b1r * GS + 48 + uu] + xo1;
            c1 = sigm(gf) * c1 + sigm(gi) * tanh_fast(gg);
            h1 = sigm(go) * tanh_fast(c1);
            hout[(b0 + 16) * 512 + hc * 16 + uu] = __float2half_rn(h1);
        }
        __syncthreads();
        if (tid == 0) {
            __threadfence();
            *((volatile int*)&g_flag[myflag]) = t + 1;
        }
        // out stores off the critical path
        size_t ob = (size_t)t * (BB * DE) + (size_t)(gq * 32 + b0) * DE + hc * 16 + uu;
        out[ob] = h0;
        out[ob + (size_t)16 * DE] = h1;
    }
}

// ---------------- launch ------------------------------------------------------
extern "C" void kernel_launch(void* const* d_in, const int* in_sizes, int n_in,
                              void* d_out, int out_size) {
    const float* x       = (const float*)d_in[0];
    const float* z       = (const float*)d_in[1];
    const float* conv0_w = (const float*)d_in[2];
    const float* conv0_b = (const float*)d_in[3];
    const float* conv1_w = (const float*)d_in[4];
    const float* conv1_b = (const float*)d_in[5];
    const float* w_ih    = (const float*)d_in[6];
    const float* w_hh    = (const float*)d_in[7];
    const float* b_ih    = (const float*)d_in[8];
    const float* b_hh    = (const float*)d_in[9];
    float* out = (float*)d_out;

    static bool attr_done = false;
    if (!attr_done) {
        cudaFuncSetAttribute(gates_gemm, cudaFuncAttributeMaxDynamicSharedMemorySize,
                             GEMM_SMEM);
        cudaFuncSetAttribute(lstm_scan, cudaFuncAttributeMaxDynamicSharedMemorySize,
                             SCAN_SMEM);
        attr_done = true;
    }

    init_state<<<64, 512>>>();
    upsample0<<<dim3(256, 128), 512>>>(z, conv0_w, conv0_b);
    upsample1<<<dim3(512, 128), 512>>>(conv1_w, conv1_b);
    pack_x<<<dim3(TST, BB), 128>>>(x);
    pack_w<<<2048, 256>>>(w_ih);
    gates_gemm<<<dim3(16, 256), 256, GEMM_SMEM>>>(b_ih, b_hh);
    lstm_scan<<<dim3(32, 4), 256, SCAN_SMEM>>>(w_hh, out);
}

// round 11
// speedup vs baseline: 1.5922x; 1.1327x over previous
#include <cuda_runtime.h>
#include <cuda_fp16.h>
#include <cstdint>

#define BB 128
#define DE 512
#define DL 256
#define G4 2048
#define TST 511

// ---------------- scratch ----------------------------------------------------
__device__ float  g_z1[256 * BB * 512];
__device__ __half g_inp[(size_t)TST * BB * 1024];   // [t][b][k]: k<512 x, else z2[t+1]
__device__ __half g_wih[2048 * 1024];
__device__ float  g_gx[(size_t)TST * BB * G4];
__device__ __half g_h[8][2][16 * 512];
__device__ int    g_flag[128];

// ---------------- helpers ----------------------------------------------------
__device__ __forceinline__ void mma_f16(float* d, const uint32_t* a,
                                        uint32_t b0, uint32_t b1) {
    asm volatile(
        "mma.sync.aligned.m16n8k16.row.col.f32.f16.f16.f32 "
        "{%0,%1,%2,%3}, {%4,%5,%6,%7}, {%8,%9}, {%0,%1,%2,%3};\n"
        : "+f"(d[0]), "+f"(d[1]), "+f"(d[2]), "+f"(d[3])
        : "r"(a[0]), "r"(a[1]), "r"(a[2]), "r"(a[3]), "r"(b0), "r"(b1));
}
__device__ __forceinline__ void ldsm4(uint32_t* r, uint32_t addr) {
    asm volatile("ldmatrix.sync.aligned.m8n8.x4.shared.b16 {%0,%1,%2,%3}, [%4];"
        : "=r"(r[0]), "=r"(r[1]), "=r"(r[2]), "=r"(r[3]) : "r"(addr));
}
__device__ __forceinline__ void cp16(uint32_t dst, const void* src) {
    asm volatile("cp.async.cg.shared.global [%0], [%1], 16;" :: "r"(dst), "l"(src));
}
__device__ __forceinline__ uint32_t smem_u32(const void* p) {
    uint32_t a;
    asm("{ .reg .u64 t; cvta.to.shared.u64 t, %1; cvt.u32.u64 %0, t; }" : "=r"(a) : "l"(p));
    return a;
}
__device__ __forceinline__ uint2 f4_to_h4(float4 v) {
    __half2 lo = __floats2half2_rn(v.x, v.y);
    __half2 hi = __floats2half2_rn(v.z, v.w);
    uint2 r;
    r.x = *reinterpret_cast<uint32_t*>(&lo);
    r.y = *reinterpret_cast<uint32_t*>(&hi);
    return r;
}
__device__ __forceinline__ float tanh_fast(float x) {
    float r; asm("tanh.approx.f32 %0, %1;" : "=f"(r) : "f"(x)); return r;
}
__device__ __forceinline__ float sigm(float x) {
    return fmaf(tanh_fast(0.5f * x), 0.5f, 0.5f);
}
__device__ __forceinline__ void st_release(int* p, int v) {
    asm volatile("st.release.gpu.global.s32 [%0], %1;" :: "l"(p), "r"(v) : "memory");
}
__device__ __forceinline__ int ld_acquire(const int* p) {
    int v;
    asm volatile("ld.acquire.gpu.global.s32 %0, [%1];" : "=r"(v) : "l"(p) : "memory");
    return v;
}

// ---------------- upsample convs ---------------------------------------------
__global__ void upsample0(const float* __restrict__ z, const float* __restrict__ w,
                          const float* __restrict__ bias) {
    int c = threadIdx.x, t2 = blockIdx.x, b = blockIdx.y;
    int ch = ((t2 & 1) << 9) + c;
    int l = t2 >> 1;
    int ic = ch >> 2;
    float acc = bias[ch];
#pragma unroll
    for (int k = 0; k < 7; k++) {
        int li = l + k - 3;
        if (li >= 0 && li < 128)
            acc += w[ch * 7 + k] * z[((size_t)li * BB + b) * DL + ic];
    }
    g_z1[((size_t)t2 * BB + b) * 512 + c] = fmaxf(acc, 0.0f);
}

__global__ void upsample1(const float* __restrict__ w, const float* __restrict__ bias) {
    int c = threadIdx.x, t2 = blockIdx.x, b = blockIdx.y;
    int ch = ((t2 & 1) << 9) + c;
    int l = t2 >> 1;
    int ic = ch >> 1;
    float acc = bias[ch];
#pragma unroll
    for (int k = 0; k < 7; k++) {
        int li = l + k - 3;
        if (li >= 0 && li < 256)
            acc += w[ch * 7 + k] * g_z1[((size_t)li * BB + b) * 512 + ic];
    }
    if (t2 >= 1)
        g_inp[((size_t)(t2 - 1) * BB + b) * 1024 + 512 + c] =
            __float2half_rn(fmaxf(acc, 0.0f));
}

// ---------------- pack kernels ------------------------------------------------
__global__ void pack_x(const float* __restrict__ x) {
    int t = blockIdx.x, b = blockIdx.y;
    int c4 = threadIdx.x << 2;
    float4 v = *reinterpret_cast<const float4*>(x + ((size_t)t * BB + b) * DE + c4);
    *reinterpret_cast<uint2*>(&g_inp[((size_t)t * BB + b) * 1024 + c4]) = f4_to_h4(v);
}
__global__ void pack_w(const float* __restrict__ w_ih) {
    int row = blockIdx.x;
    int c4 = threadIdx.x << 2;
    float4 v = *reinterpret_cast<const float4*>(w_ih + (size_t)row * 1024 + c4);
    *reinterpret_cast<uint2*>(&g_wih[(size_t)row * 1024 + c4]) = f4_to_h4(v);
}

// ---------------- gates_x GEMM (fp16 m16n8k16, 3-stage cp.async) -------------
#define HSTR 40
#define ABYTES (256 * HSTR * 2)
#define BUFB   (ABYTES + 128 * HSTR * 2)
#define GEMM_SMEM (3 * BUFB)

__global__ void __launch_bounds__(256, 1)
gates_gemm(const float* __restrict__ b_ih, const float* __restrict__ b_hh) {
    extern __shared__ char smc[];
    const uint32_t smb = smem_u32(smc);

    const int n0 = blockIdx.x << 7;
    const int t0 = blockIdx.y << 1;
    const int tid = threadIdx.x;
    const int warp = tid >> 5, lane = tid & 31;
    const int gid = lane >> 2, tg = lane & 3;
    const int wm = (warp >> 1) << 6;
    const int wn = (warp & 1) << 6;

    const uint32_t lrow = (lane & 15);
    const uint32_t lcol = (lane >> 4) << 4;
    const uint32_t a_base = smb + (wm + lrow) * (HSTR * 2) + lcol;
    const uint32_t b_base = smb + ABYTES + (wn + lrow) * (HSTR * 2) + lcol;

    float acc[4][8][4];
#pragma unroll
    for (int mi = 0; mi < 4; mi++)
#pragma unroll
        for (int ni = 0; ni < 8; ni++)
#pragma unroll
            for (int cc = 0; cc < 4; cc++) acc[mi][ni][cc] = 0.0f;

    const int ar = tid;
    int atr = t0 + (ar >> 7); if (atr > TST - 1) atr = TST - 1;
    const __half* asrc0 = g_inp + ((size_t)atr * BB + (ar & 127)) * 1024;
    const uint32_t adst0 = smb + ar * (HSTR * 2);
    const int brow = tid >> 1, bseg = tid & 1;
    const __half* bsrc0 = g_wih + (size_t)(n0 + brow) * 1024 + bseg * 16;
    const uint32_t bdst0 = smb + ABYTES + brow * (HSTR * 2) + bseg * 32;

    auto issue = [&](int it) {
        const uint32_t bo = (it % 3) * BUFB;
        const int kb = it << 5;
        cp16(adst0 + bo,      asrc0 + kb);
        cp16(adst0 + bo + 16, asrc0 + kb + 8);
        cp16(adst0 + bo + 32, asrc0 + kb + 16);
        cp16(adst0 + bo + 48, asrc0 + kb + 24);
        cp16(bdst0 + bo,      bsrc0 + kb);
        cp16(bdst0 + bo + 16, bsrc0 + kb + 8);
        asm volatile("cp.async.commit_group;");
    };

    issue(0);
    issue(1);

#pragma unroll 1
    for (int it = 0; it < 32; ++it) {
        if (it < 30) {
            asm volatile("cp.async.wait_group 1;" ::: "memory");
        } else {
            asm volatile("cp.async.wait_group 0;" ::: "memory");
        }
        __syncthreads();
        if (it + 2 < 32) issue(it + 2);
        const uint32_t bo = (it % 3) * BUFB;
#pragma unroll
        for (int kc = 0; kc < 2; kc++) {
            uint32_t Af[4][4], Bf[4][4];
#pragma unroll
            for (int mi = 0; mi < 4; mi++)
                ldsm4(Af[mi], a_base + bo + mi * (16 * HSTR * 2) + kc * 32);
#pragma unroll
            for (int p = 0; p < 4; p++)
                ldsm4(Bf[p], b_base + bo + p * (16 * HSTR * 2) + kc * 32);
#pragma unroll
            for (int mi = 0; mi < 4; mi++)
#pragma unroll
                for (int p = 0; p < 4; p++) {
                    mma_f16(acc[mi][2 * p],     Af[mi], Bf[p][0], Bf[p][2]);
                    mma_f16(acc[mi][2 * p + 1], Af[mi], Bf[p][1], Bf[p][3]);
                }
        }
    }

#pragma unroll
    for (int mi = 0; mi < 4; mi++) {
        int rb = wm + mi * 16;
        int tr = t0 + (rb >> 7);
        if (tr >= TST) continue;
        int r = rb + gid;
#pragma unroll
        for (int ni = 0; ni < 8; ni++) {
            int cb = n0 + wn + ni * 8 + 2 * tg;
            float bb0 = b_ih[cb] + b_hh[cb];
            float bb1 = b_ih[cb + 1] + b_hh[cb + 1];
            size_t base = ((size_t)tr * BB + (r & 127)) * G4 + cb;
            *reinterpret_cast<float2*>(g_gx + base) =
                make_float2(acc[mi][ni][0] + bb0, acc[mi][ni][1] + bb1);
            *reinterpret_cast<float2*>(g_gx + base + (size_t)8 * G4) =
                make_float2(acc[mi][ni][2] + bb0, acc[mi][ni][3] + bb1);
        }
    }
}

// ---------------- init -------------------------------------------------------
__global__ void init_state() {
    int idx = blockIdx.x * blockDim.x + threadIdx.x;
    uint32_t* hf = reinterpret_cast<uint32_t*>(&g_h[0][0][0]);
    for (int i = idx; i < 8 * 2 * 16 * 256; i += gridDim.x * blockDim.x) hf[i] = 0u;
    if (idx < 128) g_flag[idx] = 0;
}

// ---------------- persistent LSTM scan (fp16) --------------------------------
// grid (16 hidden-chunks, 8 batch-groups). CTA: M=16 batch, N=128 gate rows
// (32 units x 4 gates, row = u*4+gate), K=512. 3 syncs/step, shuffle epilogue.
#define WST 520                          // halves per row
#define WST2 (WST * 2)                   // bytes per row
#define WSM_B (128 * WST2)               // 133120
#define HSM_B (16 * WST2)                // 16640
#define SCAN_SMEM (WSM_B + HSM_B)

__global__ void __launch_bounds__(256, 1)
lstm_scan(const float* __restrict__ w_hh, float* __restrict__ out) {
    extern __shared__ char smc[];
    __half* wsm = reinterpret_cast<__half*>(smc);
    __half* hsm = reinterpret_cast<__half*>(smc + WSM_B);
    const uint32_t smb_w = smem_u32(wsm);
    const uint32_t smb_h = smem_u32(hsm);

    const int hc = blockIdx.x;            // hidden chunk 0..15 (32 units each)
    const int gq = blockIdx.y;            // batch group 0..7 (16 rows each)
    const int tid = threadIdx.x;
    const int warp = tid >> 5, lane = tid & 31;
    const int gid = lane >> 2, tg = lane & 3;
    const int wn = warp << 4;             // local col base (units 4*warp..+3)

    const uint32_t lrow = (lane & 15);
    const uint32_t lcol = (lane >> 4) << 4;
    const uint32_t ha = smb_h + lrow * WST2 + lcol;
    const uint32_t wa = smb_w + (wn + lrow) * WST2 + lcol;

    // load w_hh slice: local row = u*4+gate (u 0..31), k 0..511, fp32 -> fp16
#pragma unroll 4
    for (int i = 0; i < 64; i++) {
        int j = tid + i * 256;            // float4 idx, 16384 total
        int row = j >> 7;                 // 0..127
        int c4 = (j & 127) << 2;
        int gate = row & 3, u = row >> 2;
        float4 v = *reinterpret_cast<const float4*>(
            w_hh + (size_t)(gate * 512 + hc * 32 + u) * 512 + c4);
        *reinterpret_cast<uint2*>(&wsm[row * WST + c4]) = f4_to_h4(v);
    }
    __syncthreads();

    // this thread's epilogue ownership: unit UL within warp's 4, rows gid,gid+8
    const int UL = ((tg & 1) << 1) | (tg >> 1);
    const int u_abs = hc * 32 + (warp << 2) + UL;
    const bool even = ((tg & 1) == 0);
    float c_lo = 0.0f, c_hi = 0.0f;
    const int myflag = (gq << 4) + hc;

    for (int t = 0; t < TST; t++) {
        const int p = t & 1;

        // prefetch gx: 2 rows x 4 gates
        size_t gxr = ((size_t)t * BB + (gq << 4) + gid) * G4;
        float xi0 = __ldcs(g_gx + gxr + u_abs);
        float xf0 = __ldcs(g_gx + gxr + 512 + u_abs);
        float xg0 = __ldcs(g_gx + gxr + 1024 + u_abs);
        float xo0 = __ldcs(g_gx + gxr + 1536 + u_abs);
        size_t gxr1 = gxr + (size_t)8 * G4;
        float xi1 = __ldcs(g_gx + gxr1 + u_abs);
        float xf1 = __ldcs(g_gx + gxr1 + 512 + u_abs);
        float xg1 = __ldcs(g_gx + gxr1 + 1024 + u_abs);
        float xo1 = __ldcs(g_gx + gxr1 + 1536 + u_abs);

        // group barrier: warp0 acquire-polls the 16 flags of its group
        if (t > 0 && warp == 0) {
            const int* fp = &g_flag[(gq << 4) + (lane & 15)];
            while (!__all_sync(0xffffffffu, ld_acquire(fp) >= t)) { }
        }
        __syncthreads();                                       // sync A

        // stage h (16 x 512 fp16 = 16KB) via cp.async.cg
        {
            const __half* hsrc = g_h[gq][p];
#pragma unroll
            for (int i = 0; i < 4; i++) {
                int j = tid + i * 256;    // 16B chunks, 1024 total
                int row = j >> 6, c8 = (j & 63) << 3;
                cp16(smb_h + row * WST2 + c8 * 2, hsrc + (row << 9) + c8);
            }
            asm volatile("cp.async.commit_group;");
            asm volatile("cp.async.wait_group 0;" ::: "memory");
        }
        __syncthreads();                                       // sync B

        // gates = h @ w_slice^T  (warp: M16 x N16, K=512)
        float acc0[4] = {0.f, 0.f, 0.f, 0.f};
        float acc1[4] = {0.f, 0.f, 0.f, 0.f};
#pragma unroll 8
        for (int kc = 0; kc < 32; kc++) {
            uint32_t Ah[4], Bw[4];
            ldsm4(Ah, ha + kc * 32);
            ldsm4(Bw, wa + kc * 32);
            mma_f16(acc0, Ah, Bw[0], Bw[2]);
            mma_f16(acc1, Ah, Bw[1], Bw[3]);
        }

        // exchange: even.acc1 <-> odd.acc0 via shfl.xor lane^1
        float r0, r1, r2, r3;
        {
            float v0 = even ? acc1[0] : acc0[0];
            float v1 = even ? acc1[1] : acc0[1];
            float v2 = even ? acc1[2] : acc0[2];
            float v3 = even ? acc1[3] : acc0[3];
            r0 = __shfl_xor_sync(0xffffffffu, v0, 1);
            r1 = __shfl_xor_sync(0xffffffffu, v1, 1);
            r2 = __shfl_xor_sync(0xffffffffu, v2, 1);
            r3 = __shfl_xor_sync(0xffffffffu, v3, 1);
        }
        // gates for (row gid): even: i=acc0[0] f=acc0[1] g=r0 o=r1
        //                      odd:  i=r0 f=r1 g=acc1[0] o=acc1[1]
        float gi0 = even ? acc0[0] : r0;
        float gf0 = even ? acc0[1] : r1;
        float gg0 = even ? r0 : acc1[0];
        float go0 = even ? r1 : acc1[1];
        float gi1 = even ? acc0[2] : r2;
        float gf1 = even ? acc0[3] : r3;
        float gg1 = even ? r2 : acc1[2];
        float go1 = even ? r3 : acc1[3];

        // epilogue
        __half* hout = g_h[gq][p ^ 1];
        float h0, h1;
        {
            float gi = gi0 + xi0, gf = gf0 + xf0, gg = gg0 + xg0, go = go0 + xo0;
            c_lo = sigm(gf) * c_lo + sigm(gi) * tanh_fast(gg);
            h0 = sigm(go) * tanh_fast(c_lo);
            hout[(gid << 9) + u_abs] = __float2half_rn(h0);
        }
        {
            float gi = gi1 + xi1, gf = gf1 + xf1, gg = gg1 + xg1, go = go1 + xo1;
            c_hi = sigm(gf) * c_hi + sigm(gi) * tanh_fast(gg);
            h1 = sigm(go) * tanh_fast(c_hi);
            hout[((gid + 8) << 9) + u_abs] = __float2half_rn(h1);
        }
        __syncthreads();                                       // sync C
        if (tid == 0) st_release(&g_flag[myflag], t + 1);

        // out stores off the critical path
        size_t ob = (size_t)t * (BB * DE) + (size_t)((gq << 4) + gid) * DE + u_abs;
        out[ob] = h0;
        out[ob + (size_t)8 * DE] = h1;
    }
}

// ---------------- launch ------------------------------------------------------
extern "C" void kernel_launch(void* const* d_in, const int* in_sizes, int n_in,
                              void* d_out, int out_size) {
    const float* x       = (const float*)d_in[0];
    const float* z       = (const float*)d_in[1];
    const float* conv0_w = (const float*)d_in[2];
    const float* conv0_b = (const float*)d_in[3];
    const float* conv1_w = (const float*)d_in[4];
    const float* conv1_b = (const float*)d_in[5];
    const float* w_ih    = (const float*)d_in[6];
    const float* w_hh    = (const float*)d_in[7];
    const float* b_ih    = (const float*)d_in[8];
    const float* b_hh    = (const float*)d_in[9];
    float* out = (float*)d_out;

    static bool attr_done = false;
    if (!attr_done) {
        cudaFuncSetAttribute(gates_gemm, cudaFuncAttributeMaxDynamicSharedMemorySize,
                             GEMM_SMEM);
        cudaFuncSetAttribute(lstm_scan, cudaFuncAttributeMaxDynamicSharedMemorySize,
                             SCAN_SMEM);
        attr_done = true;
    }

    init_state<<<64, 512>>>();
    upsample0<<<dim3(256, 128), 512>>>(z, conv0_w, conv0_b);
    upsample1<<<dim3(512, 128), 512>>>(conv1_w, conv1_b);
    pack_x<<<dim3(TST, BB), 128>>>(x);
    pack_w<<<2048, 256>>>(w_ih);
    gates_gemm<<<dim3(16, 256), 256, GEMM_SMEM>>>(b_ih, b_hh);
    lstm_scan<<<dim3(16, 8), 256, SCAN_SMEM>>>(w_hh, out);
}

// round 12
// speedup vs baseline: 1.6984x; 1.0667x over previous
#include <cuda_runtime.h>
#include <cuda_fp16.h>
#include <cstdint>

#define BB 128
#define DE 512
#define DL 256
#define G4 2048
#define TST 511

// ---------------- scratch ----------------------------------------------------
__device__ float  g_z1[256 * BB * 512];
__device__ __half g_inp[(size_t)TST * BB * 1024];   // [t][b][k]: k<512 x, else z2[t+1]
__device__ __half g_wih[2048 * 1024];
__device__ float  g_gx[(size_t)TST * BB * G4];
__device__ __half g_h[8][2][16 * 512];
__device__ int    g_flag[128];

// ---------------- helpers ----------------------------------------------------
__device__ __forceinline__ void mma_f16(float* d, const uint32_t* a,
                                        uint32_t b0, uint32_t b1) {
    asm volatile(
        "mma.sync.aligned.m16n8k16.row.col.f32.f16.f16.f32 "
        "{%0,%1,%2,%3}, {%4,%5,%6,%7}, {%8,%9}, {%0,%1,%2,%3};\n"
        : "+f"(d[0]), "+f"(d[1]), "+f"(d[2]), "+f"(d[3])
        : "r"(a[0]), "r"(a[1]), "r"(a[2]), "r"(a[3]), "r"(b0), "r"(b1));
}
__device__ __forceinline__ void ldsm4(uint32_t* r, uint32_t addr) {
    asm volatile("ldmatrix.sync.aligned.m8n8.x4.shared.b16 {%0,%1,%2,%3}, [%4];"
        : "=r"(r[0]), "=r"(r[1]), "=r"(r[2]), "=r"(r[3]) : "r"(addr));
}
__device__ __forceinline__ void cp16(uint32_t dst, const void* src) {
    asm volatile("cp.async.cg.shared.global [%0], [%1], 16;" :: "r"(dst), "l"(src));
}
__device__ __forceinline__ uint32_t smem_u32(const void* p) {
    uint32_t a;
    asm("{ .reg .u64 t; cvta.to.shared.u64 t, %1; cvt.u32.u64 %0, t; }" : "=r"(a) : "l"(p));
    return a;
}
__device__ __forceinline__ uint2 f4_to_h4(float4 v) {
    __half2 lo = __floats2half2_rn(v.x, v.y);
    __half2 hi = __floats2half2_rn(v.z, v.w);
    uint2 r;
    r.x = *reinterpret_cast<uint32_t*>(&lo);
    r.y = *reinterpret_cast<uint32_t*>(&hi);
    return r;
}
__device__ __forceinline__ float tanh_fast(float x) {
    float r; asm("tanh.approx.f32 %0, %1;" : "=f"(r) : "f"(x)); return r;
}
__device__ __forceinline__ float sigm(float x) {
    return fmaf(tanh_fast(0.5f * x), 0.5f, 0.5f);
}
__device__ __forceinline__ void st_release(int* p, int v) {
    asm volatile("st.release.gpu.global.s32 [%0], %1;" :: "l"(p), "r"(v) : "memory");
}
__device__ __forceinline__ int ld_acquire(const int* p) {
    int v;
    asm volatile("ld.acquire.gpu.global.s32 %0, [%1];" : "=r"(v) : "l"(p) : "memory");
    return v;
}

// ---------------- upsample convs ---------------------------------------------
__global__ void upsample0(const float* __restrict__ z, const float* __restrict__ w,
                          const float* __restrict__ bias) {
    int c = threadIdx.x, t2 = blockIdx.x, b = blockIdx.y;
    int ch = ((t2 & 1) << 9) + c;
    int l = t2 >> 1;
    int ic = ch >> 2;
    float acc = bias[ch];
#pragma unroll
    for (int k = 0; k < 7; k++) {
        int li = l + k - 3;
        if (li >= 0 && li < 128)
            acc += w[ch * 7 + k] * z[((size_t)li * BB + b) * DL + ic];
    }
    g_z1[((size_t)t2 * BB + b) * 512 + c] = fmaxf(acc, 0.0f);
}

__global__ void upsample1(const float* __restrict__ w, const float* __restrict__ bias) {
    int c = threadIdx.x, t2 = blockIdx.x, b = blockIdx.y;
    int ch = ((t2 & 1) << 9) + c;
    int l = t2 >> 1;
    int ic = ch >> 1;
    float acc = bias[ch];
#pragma unroll
    for (int k = 0; k < 7; k++) {
        int li = l + k - 3;
        if (li >= 0 && li < 256)
            acc += w[ch * 7 + k] * g_z1[((size_t)li * BB + b) * 512 + ic];
    }
    if (t2 >= 1)
        g_inp[((size_t)(t2 - 1) * BB + b) * 1024 + 512 + c] =
            __float2half_rn(fmaxf(acc, 0.0f));
}

// ---------------- pack kernels ------------------------------------------------
__global__ void pack_x(const float* __restrict__ x) {
    int t = blockIdx.x, b = blockIdx.y;
    int c4 = threadIdx.x << 2;
    float4 v = *reinterpret_cast<const float4*>(x + ((size_t)t * BB + b) * DE + c4);
    *reinterpret_cast<uint2*>(&g_inp[((size_t)t * BB + b) * 1024 + c4]) = f4_to_h4(v);
}
__global__ void pack_w(const float* __restrict__ w_ih) {
    int row = blockIdx.x;
    int c4 = threadIdx.x << 2;
    float4 v = *reinterpret_cast<const float4*>(w_ih + (size_t)row * 1024 + c4);
    *reinterpret_cast<uint2*>(&g_wih[(size_t)row * 1024 + c4]) = f4_to_h4(v);
}

// ---------------- gates_x GEMM (fp16, 2 CTAs/SM) ------------------------------
// CTA: 128 rows (1 timestep) x 128 n, BK=32, 8 warps (2m x 4n), warp 64x32.
// 3-stage cp.async pipeline; low regs (acc=64) so 2 CTAs co-reside per SM.
#define HSTR 40                       // halves per row (80B)
#define STG  (256 * HSTR * 2)         // stage bytes: 128 A rows + 128 B rows = 20480
#define BOFF (128 * HSTR * 2)         // B offset within stage = 10240
#define GEMM_SMEM (3 * STG)           // 61440

__global__ void __launch_bounds__(256, 2)
gates_gemm(const float* __restrict__ b_ih, const float* __restrict__ b_hh) {
    extern __shared__ char smc[];
    const uint32_t smb = smem_u32(smc);

    const int n0 = blockIdx.x << 7;
    const int t  = blockIdx.y;
    const int tid = threadIdx.x;
    const int warp = tid >> 5, lane = tid & 31;
    const int gid = lane >> 2, tg = lane & 3;
    const int wm = (warp & 1) << 6;    // row base 0/64
    const int wn = (warp >> 1) << 5;   // n base 0/32/64/96

    const uint32_t lrow = (lane & 15);
    const uint32_t lcol = (lane >> 4) << 4;
    const uint32_t a_base = smb + (wm + lrow) * (HSTR * 2) + lcol;
    const uint32_t b_base = smb + BOFF + (wn + lrow) * (HSTR * 2) + lcol;

    float acc[4][4][4];
#pragma unroll
    for (int mi = 0; mi < 4; mi++)
#pragma unroll
        for (int ni = 0; ni < 4; ni++)
#pragma unroll
            for (int cc = 0; cc < 4; cc++) acc[mi][ni][cc] = 0.0f;

    const int arow = tid >> 1, aseg = tid & 1;
    const __half* asrc0 = g_inp + ((size_t)t * BB + arow) * 1024 + aseg * 16;
    const __half* bsrc0 = g_wih + (size_t)(n0 + arow) * 1024 + aseg * 16;
    const uint32_t adst0 = smb + arow * (HSTR * 2) + aseg * 32;
    const uint32_t bdst0 = smb + BOFF + arow * (HSTR * 2) + aseg * 32;

    auto issue = [&](int it) {
        const uint32_t bo = (it % 3) * STG;
        const int kb = it << 5;
        cp16(adst0 + bo,      asrc0 + kb);
        cp16(adst0 + bo + 16, asrc0 + kb + 8);
        cp16(bdst0 + bo,      bsrc0 + kb);
        cp16(bdst0 + bo + 16, bsrc0 + kb + 8);
        asm volatile("cp.async.commit_group;");
    };

    issue(0);
    issue(1);

#pragma unroll 1
    for (int it = 0; it < 32; ++it) {
        if (it < 30) {
            asm volatile("cp.async.wait_group 1;" ::: "memory");
        } else {
            asm volatile("cp.async.wait_group 0;" ::: "memory");
        }
        __syncthreads();
        if (it + 2 < 32) issue(it + 2);
        const uint32_t bo = (it % 3) * STG;
#pragma unroll
        for (int kc = 0; kc < 2; kc++) {
            uint32_t Af[4][4], Bf[2][4];
#pragma unroll
            for (int mi = 0; mi < 4; mi++)
                ldsm4(Af[mi], a_base + bo + mi * (16 * HSTR * 2) + kc * 32);
#pragma unroll
            for (int p = 0; p < 2; p++)
                ldsm4(Bf[p], b_base + bo + p * (16 * HSTR * 2) + kc * 32);
#pragma unroll
            for (int mi = 0; mi < 4; mi++)
#pragma unroll
                for (int p = 0; p < 2; p++) {
                    mma_f16(acc[mi][2 * p],     Af[mi], Bf[p][0], Bf[p][2]);
                    mma_f16(acc[mi][2 * p + 1], Af[mi], Bf[p][1], Bf[p][3]);
                }
        }
    }

    // epilogue
#pragma unroll
    for (int mi = 0; mi < 4; mi++) {
        int r = wm + mi * 16 + gid;
#pragma unroll
        for (int ni = 0; ni < 4; ni++) {
            int cb = n0 + wn + ni * 8 + 2 * tg;
            float bb0 = b_ih[cb] + b_hh[cb];
            float bb1 = b_ih[cb + 1] + b_hh[cb + 1];
            size_t base = ((size_t)t * BB + r) * G4 + cb;
            *reinterpret_cast<float2*>(g_gx + base) =
                make_float2(acc[mi][ni][0] + bb0, acc[mi][ni][1] + bb1);
            *reinterpret_cast<float2*>(g_gx + base + (size_t)8 * G4) =
                make_float2(acc[mi][ni][2] + bb0, acc[mi][ni][3] + bb1);
        }
    }
}

// ---------------- init -------------------------------------------------------
__global__ void init_state() {
    int idx = blockIdx.x * blockDim.x + threadIdx.x;
    uint32_t* hf = reinterpret_cast<uint32_t*>(&g_h[0][0][0]);
    for (int i = idx; i < 8 * 2 * 16 * 256; i += gridDim.x * blockDim.x) hf[i] = 0u;
    if (idx < 128) g_flag[idx] = 0;
}

// ---------------- persistent LSTM scan (fp16, split-K h staging) --------------
// grid (16 hidden-chunks, 8 batch-groups). CTA: M=16 batch, N=128 gate rows
// (row = u*4+gate), K=512. Shuffle epilogue; h staged in 2 overlapping halves.
#define WST 520
#define WST2 (WST * 2)
#define WSM_B (128 * WST2)               // 133120
#define HSM_B (16 * WST2)                // 16640
#define SCAN_SMEM (WSM_B + HSM_B)

__global__ void __launch_bounds__(256, 1)
lstm_scan(const float* __restrict__ w_hh, float* __restrict__ out) {
    extern __shared__ char smc[];
    __half* wsm = reinterpret_cast<__half*>(smc);
    __half* hsm = reinterpret_cast<__half*>(smc + WSM_B);
    const uint32_t smb_w = smem_u32(wsm);
    const uint32_t smb_h = smem_u32(hsm);

    const int hc = blockIdx.x;
    const int gq = blockIdx.y;
    const int tid = threadIdx.x;
    const int warp = tid >> 5, lane = tid & 31;
    const int gid = lane >> 2, tg = lane & 3;
    const int wn = warp << 4;

    const uint32_t lrow = (lane & 15);
    const uint32_t lcol = (lane >> 4) << 4;
    const uint32_t ha = smb_h + lrow * WST2 + lcol;
    const uint32_t wa = smb_w + (wn + lrow) * WST2 + lcol;

    // load w_hh slice: local row = u*4+gate, fp32 -> fp16
#pragma unroll 4
    for (int i = 0; i < 64; i++) {
        int j = tid + i * 256;
        int row = j >> 7;
        int c4 = (j & 127) << 2;
        int gate = row & 3, u = row >> 2;
        float4 v = *reinterpret_cast<const float4*>(
            w_hh + (size_t)(gate * 512 + hc * 32 + u) * 512 + c4);
        *reinterpret_cast<uint2*>(&wsm[row * WST + c4]) = f4_to_h4(v);
    }
    __syncthreads();

    const int UL = ((tg & 1) << 1) | (tg >> 1);
    const int u_abs = hc * 32 + (warp << 2) + UL;
    const bool even = ((tg & 1) == 0);
    float c_lo = 0.0f, c_hi = 0.0f;
    const int myflag = (gq << 4) + hc;

    for (int t = 0; t < TST; t++) {
        const int p = t & 1;

        // prefetch gx: 2 rows x 4 gates
        size_t gxr = ((size_t)t * BB + (gq << 4) + gid) * G4;
        float xi0 = __ldcs(g_gx + gxr + u_abs);
        float xf0 = __ldcs(g_gx + gxr + 512 + u_abs);
        float xg0 = __ldcs(g_gx + gxr + 1024 + u_abs);
        float xo0 = __ldcs(g_gx + gxr + 1536 + u_abs);
        size_t gxr1 = gxr + (size_t)8 * G4;
        float xi1 = __ldcs(g_gx + gxr1 + u_abs);
        float xf1 = __ldcs(g_gx + gxr1 + 512 + u_abs);
        float xg1 = __ldcs(g_gx + gxr1 + 1024 + u_abs);
        float xo1 = __ldcs(g_gx + gxr1 + 1536 + u_abs);

        // group barrier
        if (t > 0 && warp == 0) {
            const int* fp = &g_flag[(gq << 4) + (lane & 15)];
            while (!__all_sync(0xffffffffu, ld_acquire(fp) >= t)) { }
        }
        __syncthreads();                                       // sync A

        // stage h in two K-halves (each 8KB) via cp.async.cg
        const __half* hsrc = g_h[gq][p];
#pragma unroll
        for (int half = 0; half < 2; half++) {
#pragma unroll
            for (int i = 0; i < 2; i++) {
                int j = tid + i * 256;        // 512 chunks per half
                int row = j >> 5, c8 = ((j & 31) + half * 32) << 3;
                cp16(smb_h + row * WST2 + c8 * 2, hsrc + (row << 9) + c8);
            }
            asm volatile("cp.async.commit_group;");
        }
        asm volatile("cp.async.wait_group 1;" ::: "memory");
        __syncthreads();                                       // sync B1

        float acc0[4] = {0.f, 0.f, 0.f, 0.f};
        float acc1[4] = {0.f, 0.f, 0.f, 0.f};
#pragma unroll 8
        for (int kc = 0; kc < 16; kc++) {
            uint32_t Ah[4], Bw[4];
            ldsm4(Ah, ha + kc * 32);
            ldsm4(Bw, wa + kc * 32);
            mma_f16(acc0, Ah, Bw[0], Bw[2]);
            mma_f16(acc1, Ah, Bw[1], Bw[3]);
        }
        asm volatile("cp.async.wait_group 0;" ::: "memory");
        __syncthreads();                                       // sync B2
#pragma unroll 8
        for (int kc = 16; kc < 32; kc++) {
            uint32_t Ah[4], Bw[4];
            ldsm4(Ah, ha + kc * 32);
            ldsm4(Bw, wa + kc * 32);
            mma_f16(acc0, Ah, Bw[0], Bw[2]);
            mma_f16(acc1, Ah, Bw[1], Bw[3]);
        }

        // exchange even.acc1 <-> odd.acc0 via shfl.xor lane^1
        float r0, r1, r2, r3;
        {
            float v0 = even ? acc1[0] : acc0[0];
            float v1 = even ? acc1[1] : acc0[1];
            float v2 = even ? acc1[2] : acc0[2];
            float v3 = even ? acc1[3] : acc0[3];
            r0 = __shfl_xor_sync(0xffffffffu, v0, 1);
            r1 = __shfl_xor_sync(0xffffffffu, v1, 1);
            r2 = __shfl_xor_sync(0xffffffffu, v2, 1);
            r3 = __shfl_xor_sync(0xffffffffu, v3, 1);
        }
        float gi0 = even ? acc0[0] : r0;
        float gf0 = even ? acc0[1] : r1;
        float gg0 = even ? r0 : acc1[0];
        float go0 = even ? r1 : acc1[1];
        float gi1 = even ? acc0[2] : r2;
        float gf1 = even ? acc0[3] : r3;
        float gg1 = even ? r2 : acc1[2];
        float go1 = even ? r3 : acc1[3];

        // epilogue
        __half* hout = g_h[gq][p ^ 1];
        float h0, h1;
        {
            float gi = gi0 + xi0, gf = gf0 + xf0, gg = gg0 + xg0, go = go0 + xo0;
            c_lo = sigm(gf) * c_lo + sigm(gi) * tanh_fast(gg);
            h0 = sigm(go) * tanh_fast(c_lo);
            hout[(gid << 9) + u_abs] = __float2half_rn(h0);
        }
        {
            float gi = gi1 + xi1, gf = gf1 + xf1, gg = gg1 + xg1, go = go1 + xo1;
            c_hi = sigm(gf) * c_hi + sigm(gi) * tanh_fast(gg);
            h1 = sigm(go) * tanh_fast(c_hi);
            hout[((gid + 8) << 9) + u_abs] = __float2half_rn(h1);
        }
        __syncthreads();                                       // sync C
        if (tid == 0) st_release(&g_flag[myflag], t + 1);

        size_t ob = (size_t)t * (BB * DE) + (size_t)((gq << 4) + gid) * DE + u_abs;
        out[ob] = h0;
        out[ob + (size_t)8 * DE] = h1;
    }
}

// ---------------- launch ------------------------------------------------------
extern "C" void kernel_launch(void* const* d_in, const int* in_sizes, int n_in,
                              void* d_out, int out_size) {
    const float* x       = (const float*)d_in[0];
    const float* z       = (const float*)d_in[1];
    const float* conv0_w = (const float*)d_in[2];
    const float* conv0_b = (const float*)d_in[3];
    const float* conv1_w = (const float*)d_in[4];
    const float* conv1_b = (const float*)d_in[5];
    const float* w_ih    = (const float*)d_in[6];
    const float* w_hh    = (const float*)d_in[7];
    const float* b_ih    = (const float*)d_in[8];
    const float* b_hh    = (const float*)d_in[9];
    float* out = (float*)d_out;

    static bool attr_done = false;
    if (!attr_done) {
        cudaFuncSetAttribute(gates_gemm, cudaFuncAttributeMaxDynamicSharedMemorySize,
                             GEMM_SMEM);
        cudaFuncSetAttribute(lstm_scan, cudaFuncAttributeMaxDynamicSharedMemorySize,
                             SCAN_SMEM);
        attr_done = true;
    }

    init_state<<<64, 512>>>();
    upsample0<<<dim3(256, 128), 512>>>(z, conv0_w, conv0_b);
    upsample1<<<dim3(512, 128), 512>>>(conv1_w, conv1_b);
    pack_x<<<dim3(TST, BB), 128>>>(x);
    pack_w<<<2048, 256>>>(w_ih);
    gates_gemm<<<dim3(16, TST), 256, GEMM_SMEM>>>(b_ih, b_hh);
    lstm_scan<<<dim3(16, 8), 256, SCAN_SMEM>>>(w_hh, out);
}

// round 13
// speedup vs baseline: 1.8060x; 1.0634x over previous
#include <cuda_runtime.h>
#include <cuda_fp16.h>
#include <cstdint>

#define BB 128
#define DE 512
#define DL 256
#define G4 2048
#define TST 511

// ---------------- scratch ----------------------------------------------------
__device__ float  g_z1[256 * BB * 512];
__device__ __half g_inp[(size_t)TST * BB * 1024];   // [t][b][k]: k<512 x, else z2[t+1]
__device__ __half g_wih[2048 * 1024];
__device__ float  g_gx[(size_t)TST * BB * G4];
__device__ __half g_h[8][2][16 * 512];
__device__ int    g_flag[128];
__device__ int    g_gxdone[TST];

// ---------------- helpers ----------------------------------------------------
__device__ __forceinline__ void mma_f16(float* d, const uint32_t* a,
                                        uint32_t b0, uint32_t b1) {
    asm volatile(
        "mma.sync.aligned.m16n8k16.row.col.f32.f16.f16.f32 "
        "{%0,%1,%2,%3}, {%4,%5,%6,%7}, {%8,%9}, {%0,%1,%2,%3};\n"
        : "+f"(d[0]), "+f"(d[1]), "+f"(d[2]), "+f"(d[3])
        : "r"(a[0]), "r"(a[1]), "r"(a[2]), "r"(a[3]), "r"(b0), "r"(b1));
}
__device__ __forceinline__ void ldsm4(uint32_t* r, uint32_t addr) {
    asm volatile("ldmatrix.sync.aligned.m8n8.x4.shared.b16 {%0,%1,%2,%3}, [%4];"
        : "=r"(r[0]), "=r"(r[1]), "=r"(r[2]), "=r"(r[3]) : "r"(addr));
}
__device__ __forceinline__ void cp16(uint32_t dst, const void* src) {
    asm volatile("cp.async.cg.shared.global [%0], [%1], 16;" :: "r"(dst), "l"(src));
}
__device__ __forceinline__ uint32_t smem_u32(const void* p) {
    uint32_t a;
    asm("{ .reg .u64 t; cvta.to.shared.u64 t, %1; cvt.u32.u64 %0, t; }" : "=r"(a) : "l"(p));
    return a;
}
__device__ __forceinline__ uint2 f4_to_h4(float4 v) {
    __half2 lo = __floats2half2_rn(v.x, v.y);
    __half2 hi = __floats2half2_rn(v.z, v.w);
    uint2 r;
    r.x = *reinterpret_cast<uint32_t*>(&lo);
    r.y = *reinterpret_cast<uint32_t*>(&hi);
    return r;
}
__device__ __forceinline__ float tanh_fast(float x) {
    float r; asm("tanh.approx.f32 %0, %1;" : "=f"(r) : "f"(x)); return r;
}
__device__ __forceinline__ float sigm(float x) {
    return fmaf(tanh_fast(0.5f * x), 0.5f, 0.5f);
}
__device__ __forceinline__ void st_release(int* p, int v) {
    asm volatile("st.release.gpu.global.s32 [%0], %1;" :: "l"(p), "r"(v) : "memory");
}
__device__ __forceinline__ int ld_acquire(const int* p) {
    int v;
    asm volatile("ld.acquire.gpu.global.s32 %0, [%1];" : "=r"(v) : "l"(p) : "memory");
    return v;
}
__device__ __forceinline__ void red_add_release(int* p, int v) {
    asm volatile("red.add.release.gpu.global.s32 [%0], %1;" :: "l"(p), "r"(v) : "memory");
}

// ---------------- prep: pack_w + pack_x + init --------------------------------
__global__ void prep(const float* __restrict__ x, const float* __restrict__ w_ih) {
    const int bid = blockIdx.x, tid = threadIdx.x;
    if (bid < 2048) {
        int row = bid;
#pragma unroll
        for (int s = 0; s < 2; s++) {
            int c4 = (tid + s * 128) << 2;
            float4 v = *reinterpret_cast<const float4*>(w_ih + (size_t)row * 1024 + c4);
            *reinterpret_cast<uint2*>(&g_wih[(size_t)row * 1024 + c4]) = f4_to_h4(v);
        }
    } else if (bid < 2048 + 65408) {
        int idx = bid - 2048;
        int t = idx >> 7, b = idx & 127;
        int c4 = tid << 2;
        float4 v = *reinterpret_cast<const float4*>(x + ((size_t)t * BB + b) * DE + c4);
        *reinterpret_cast<uint2*>(&g_inp[((size_t)t * BB + b) * 1024 + c4]) = f4_to_h4(v);
    } else {
        uint32_t* hf = reinterpret_cast<uint32_t*>(&g_h[0][0][0]);
        for (int i = tid; i < 8 * 2 * 16 * 256; i += 128) hf[i] = 0u;
        if (tid < 128) g_flag[tid] = 0;
        for (int i = tid; i < TST; i += 128) g_gxdone[i] = 0;
    }
}

// ---------------- upsample convs ---------------------------------------------
__global__ void upsample0(const float* __restrict__ z, const float* __restrict__ w,
                          const float* __restrict__ bias) {
    int c = threadIdx.x, t2 = blockIdx.x, b = blockIdx.y;
    int ch = ((t2 & 1) << 9) + c;
    int l = t2 >> 1;
    int ic = ch >> 2;
    float acc = bias[ch];
#pragma unroll
    for (int k = 0; k < 7; k++) {
        int li = l + k - 3;
        if (li >= 0 && li < 128)
            acc += w[ch * 7 + k] * z[((size_t)li * BB + b) * DL + ic];
    }
    g_z1[((size_t)t2 * BB + b) * 512 + c] = fmaxf(acc, 0.0f);
}

__global__ void upsample1(const float* __restrict__ w, const float* __restrict__ bias) {
    int c = threadIdx.x, t2 = blockIdx.x, b = blockIdx.y;
    int ch = ((t2 & 1) << 9) + c;
    int l = t2 >> 1;
    int ic = ch >> 1;
    float acc = bias[ch];
#pragma unroll
    for (int k = 0; k < 7; k++) {
        int li = l + k - 3;
        if (li >= 0 && li < 256)
            acc += w[ch * 7 + k] * g_z1[((size_t)li * BB + b) * 512 + ic];
    }
    if (t2 >= 1)
        g_inp[((size_t)(t2 - 1) * BB + b) * 1024 + 512 + c] =
            __float2half_rn(fmaxf(acc, 0.0f));
}

// ---------------- gates_x GEMM (fp16, 2 CTAs/SM, publishes g_gxdone) ---------
#define HSTR 40
#define STG  (256 * HSTR * 2)
#define BOFF (128 * HSTR * 2)
#define GEMM_SMEM (3 * STG)

__global__ void __launch_bounds__(256, 2)
gates_gemm(const float* __restrict__ b_ih, const float* __restrict__ b_hh) {
    extern __shared__ char smc[];
    const uint32_t smb = smem_u32(smc);

    const int n0 = blockIdx.x << 7;
    const int t  = blockIdx.y;
    const int tid = threadIdx.x;
    const int warp = tid >> 5, lane = tid & 31;
    const int gid = lane >> 2, tg = lane & 3;
    const int wm = (warp & 1) << 6;
    const int wn = (warp >> 1) << 5;

    const uint32_t lrow = (lane & 15);
    const uint32_t lcol = (lane >> 4) << 4;
    const uint32_t a_base = smb + (wm + lrow) * (HSTR * 2) + lcol;
    const uint32_t b_base = smb + BOFF + (wn + lrow) * (HSTR * 2) + lcol;

    float acc[4][4][4];
#pragma unroll
    for (int mi = 0; mi < 4; mi++)
#pragma unroll
        for (int ni = 0; ni < 4; ni++)
#pragma unroll
            for (int cc = 0; cc < 4; cc++) acc[mi][ni][cc] = 0.0f;

    const int arow = tid >> 1, aseg = tid & 1;
    const __half* asrc0 = g_inp + ((size_t)t * BB + arow) * 1024 + aseg * 16;
    const __half* bsrc0 = g_wih + (size_t)(n0 + arow) * 1024 + aseg * 16;
    const uint32_t adst0 = smb + arow * (HSTR * 2) + aseg * 32;
    const uint32_t bdst0 = smb + BOFF + arow * (HSTR * 2) + aseg * 32;

    auto issue = [&](int it) {
        const uint32_t bo = (it % 3) * STG;
        const int kb = it << 5;
        cp16(adst0 + bo,      asrc0 + kb);
        cp16(adst0 + bo + 16, asrc0 + kb + 8);
        cp16(bdst0 + bo,      bsrc0 + kb);
        cp16(bdst0 + bo + 16, bsrc0 + kb + 8);
        asm volatile("cp.async.commit_group;");
    };

    issue(0);
    issue(1);

#pragma unroll 1
    for (int it = 0; it < 32; ++it) {
        if (it < 30) {
            asm volatile("cp.async.wait_group 1;" ::: "memory");
        } else {
            asm volatile("cp.async.wait_group 0;" ::: "memory");
        }
        __syncthreads();
        if (it + 2 < 32) issue(it + 2);
        const uint32_t bo = (it % 3) * STG;
#pragma unroll
        for (int kc = 0; kc < 2; kc++) {
            uint32_t Af[4][4], Bf[2][4];
#pragma unroll
            for (int mi = 0; mi < 4; mi++)
                ldsm4(Af[mi], a_base + bo + mi * (16 * HSTR * 2) + kc * 32);
#pragma unroll
            for (int p = 0; p < 2; p++)
                ldsm4(Bf[p], b_base + bo + p * (16 * HSTR * 2) + kc * 32);
#pragma unroll
            for (int mi = 0; mi < 4; mi++)
#pragma unroll
                for (int p = 0; p < 2; p++) {
                    mma_f16(acc[mi][2 * p],     Af[mi], Bf[p][0], Bf[p][2]);
                    mma_f16(acc[mi][2 * p + 1], Af[mi], Bf[p][1], Bf[p][3]);
                }
        }
    }

    // epilogue
#pragma unroll
    for (int mi = 0; mi < 4; mi++) {
        int r = wm + mi * 16 + gid;
#pragma unroll
        for (int ni = 0; ni < 4; ni++) {
            int cb = n0 + wn + ni * 8 + 2 * tg;
            float bb0 = b_ih[cb] + b_hh[cb];
            float bb1 = b_ih[cb + 1] + b_hh[cb + 1];
            size_t base = ((size_t)t * BB + r) * G4 + cb;
            *reinterpret_cast<float2*>(g_gx + base) =
                make_float2(acc[mi][ni][0] + bb0, acc[mi][ni][1] + bb1);
            *reinterpret_cast<float2*>(g_gx + base + (size_t)8 * G4) =
                make_float2(acc[mi][ni][2] + bb0, acc[mi][ni][3] + bb1);
        }
    }

    // publish: this CTA's share of timestep t is complete
    __syncthreads();
    if (tid == 0) red_add_release(&g_gxdone[t], 1);
}

// ---------------- persistent LSTM scan (overlapped with gemm) -----------------
// grid (16 hidden-chunks, 8 batch-groups). CTA: M=16 batch, N=128 gate rows
// (row = u*4+gate), K=512. Waits g_gxdone one step ahead, folded into the
// barrier poll. Reg-capped to 128 so a gemm CTA co-resides on each SM.
#define WST 520
#define WST2 (WST * 2)
#define WSM_B (128 * WST2)               // 133120
#define HSM_B (16 * WST2)                // 16640
#define SCAN_SMEM (WSM_B + HSM_B)

__global__ void __launch_bounds__(256, 2)
lstm_scan(const float* __restrict__ w_hh, float* __restrict__ out) {
    extern __shared__ char smc[];
    __half* wsm = reinterpret_cast<__half*>(smc);
    __half* hsm = reinterpret_cast<__half*>(smc + WSM_B);
    const uint32_t smb_w = smem_u32(wsm);
    const uint32_t smb_h = smem_u32(hsm);

    const int hc = blockIdx.x;
    const int gq = blockIdx.y;
    const int tid = threadIdx.x;
    const int warp = tid >> 5, lane = tid & 31;
    const int gid = lane >> 2, tg = lane & 3;
    const int wn = warp << 4;

    const uint32_t lrow = (lane & 15);
    const uint32_t lcol = (lane >> 4) << 4;
    const uint32_t ha = smb_h + lrow * WST2 + lcol;
    const uint32_t wa = smb_w + (wn + lrow) * WST2 + lcol;

    // load w_hh slice: local row = u*4+gate, fp32 -> fp16
#pragma unroll 4
    for (int i = 0; i < 64; i++) {
        int j = tid + i * 256;
        int row = j >> 7;
        int c4 = (j & 127) << 2;
        int gate = row & 3, u = row >> 2;
        float4 v = *reinterpret_cast<const float4*>(
            w_hh + (size_t)(gate * 512 + hc * 32 + u) * 512 + c4);
        *reinterpret_cast<uint2*>(&wsm[row * WST + c4]) = f4_to_h4(v);
    }
    __syncthreads();

    // wait for gx of step 0 (gemm runs concurrently)
    if (warp == 0) {
        while (!__all_sync(0xffffffffu, ld_acquire(&g_gxdone[0]) >= 16)) { }
    }
    __syncthreads();

    const int UL = ((tg & 1) << 1) | (tg >> 1);
    const int u_abs = hc * 32 + (warp << 2) + UL;
    const bool even = ((tg & 1) == 0);
    float c_lo = 0.0f, c_hi = 0.0f;
    const int myflag = (gq << 4) + hc;

    for (int t = 0; t < TST; t++) {
        const int p = t & 1;

        // prefetch gx (readiness of step t ensured during step t-1's poll)
        size_t gxr = ((size_t)t * BB + (gq << 4) + gid) * G4;
        float xi0 = __ldcs(g_gx + gxr + u_abs);
        float xf0 = __ldcs(g_gx + gxr + 512 + u_abs);
        float xg0 = __ldcs(g_gx + gxr + 1024 + u_abs);
        float xo0 = __ldcs(g_gx + gxr + 1536 + u_abs);
        size_t gxr1 = gxr + (size_t)8 * G4;
        float xi1 = __ldcs(g_gx + gxr1 + u_abs);
        float xf1 = __ldcs(g_gx + gxr1 + 512 + u_abs);
        float xg1 = __ldcs(g_gx + gxr1 + 1024 + u_abs);
        float xo1 = __ldcs(g_gx + gxr1 + 1536 + u_abs);

        // combined poll: h-barrier for step t + gx readiness for step t+1
        if (warp == 0) {
            const bool needh = (t > 0);
            const int* fp = &g_flag[(gq << 4) + (lane & 15)];
            const int* gp = &g_gxdone[(t + 1 < TST) ? (t + 1) : t];
            while (true) {
                bool okh = !needh || (ld_acquire(fp) >= t);
                bool okg = ld_acquire(gp) >= 16;
                if (__all_sync(0xffffffffu, okh && okg)) break;
            }
        }
        __syncthreads();                                       // sync A

        // stage h in two K-halves (each 8KB) via cp.async.cg
        const __half* hsrc = g_h[gq][p];
#pragma unroll
        for (int half = 0; half < 2; half++) {
#pragma unroll
            for (int i = 0; i < 2; i++) {
                int j = tid + i * 256;
                int row = j >> 5, c8 = ((j & 31) + half * 32) << 3;
                cp16(smb_h + row * WST2 + c8 * 2, hsrc + (row << 9) + c8);
            }
            asm volatile("cp.async.commit_group;");
        }
        asm volatile("cp.async.wait_group 1;" ::: "memory");
        __syncthreads();                                       // sync B1

        float acc0[4] = {0.f, 0.f, 0.f, 0.f};
        float acc1[4] = {0.f, 0.f, 0.f, 0.f};
#pragma unroll 8
        for (int kc = 0; kc < 16; kc++) {
            uint32_t Ah[4], Bw[4];
            ldsm4(Ah, ha + kc * 32);
            ldsm4(Bw, wa + kc * 32);
            mma_f16(acc0, Ah, Bw[0], Bw[2]);
            mma_f16(acc1, Ah, Bw[1], Bw[3]);
        }
        asm volatile("cp.async.wait_group 0;" ::: "memory");
        __syncthreads();                                       // sync B2
#pragma unroll 8
        for (int kc = 16; kc < 32; kc++) {
            uint32_t Ah[4], Bw[4];
            ldsm4(Ah, ha + kc * 32);
            ldsm4(Bw, wa + kc * 32);
            mma_f16(acc0, Ah, Bw[0], Bw[2]);
            mma_f16(acc1, Ah, Bw[1], Bw[3]);
        }

        // exchange even.acc1 <-> odd.acc0 via shfl.xor lane^1
        float r0, r1, r2, r3;
        {
            float v0 = even ? acc1[0] : acc0[0];
            float v1 = even ? acc1[1] : acc0[1];
            float v2 = even ? acc1[2] : acc0[2];
            float v3 = even ? acc1[3] : acc0[3];
            r0 = __shfl_xor_sync(0xffffffffu, v0, 1);
            r1 = __shfl_xor_sync(0xffffffffu, v1, 1);
            r2 = __shfl_xor_sync(0xffffffffu, v2, 1);
            r3 = __shfl_xor_sync(0xffffffffu, v3, 1);
        }
        float gi0 = even ? acc0[0] : r0;
        float gf0 = even ? acc0[1] : r1;
        float gg0 = even ? r0 : acc1[0];
        float go0 = even ? r1 : acc1[1];
        float gi1 = even ? acc0[2] : r2;
        float gf1 = even ? acc0[3] : r3;
        float gg1 = even ? r2 : acc1[2];
        float go1 = even ? r3 : acc1[3];

        // epilogue
        __half* hout = g_h[gq][p ^ 1];
        float h0, h1;
        {
            float gi = gi0 + xi0, gf = gf0 + xf0, gg = gg0 + xg0, go = go0 + xo0;
            c_lo = sigm(gf) * c_lo + sigm(gi) * tanh_fast(gg);
            h0 = sigm(go) * tanh_fast(c_lo);
            hout[(gid << 9) + u_abs] = __float2half_rn(h0);
        }
        {
            float gi = gi1 + xi1, gf = gf1 + xf1, gg = gg1 + xg1, go = go1 + xo1;
            c_hi = sigm(gf) * c_hi + sigm(gi) * tanh_fast(gg);
            h1 = sigm(go) * tanh_fast(c_hi);
            hout[((gid + 8) << 9) + u_abs] = __float2half_rn(h1);
        }
        __syncthreads();                                       // sync C
        if (tid == 0) st_release(&g_flag[myflag], t + 1);

        size_t ob = (size_t)t * (BB * DE) + (size_t)((gq << 4) + gid) * DE + u_abs;
        out[ob] = h0;
        out[ob + (size_t)8 * DE] = h1;
    }
}

// ---------------- launch ------------------------------------------------------
extern "C" void kernel_launch(void* const* d_in, const int* in_sizes, int n_in,
                              void* d_out, int out_size) {
    const float* x       = (const float*)d_in[0];
    const float* z       = (const float*)d_in[1];
    const float* conv0_w = (const float*)d_in[2];
    const float* conv0_b = (const float*)d_in[3];
    const float* conv1_w = (const float*)d_in[4];
    const float* conv1_b = (const float*)d_in[5];
    const float* w_ih    = (const float*)d_in[6];
    const float* w_hh    = (const float*)d_in[7];
    const float* b_ih    = (const float*)d_in[8];
    const float* b_hh    = (const float*)d_in[9];
    float* out = (float*)d_out;

    static cudaStream_t s1 = nullptr, s2 = nullptr;
    static cudaEvent_t ef = nullptr, e1 = nullptr, e2 = nullptr;
    if (!s1) {
        cudaStreamCreateWithFlags(&s1, cudaStreamNonBlocking);
        cudaStreamCreateWithFlags(&s2, cudaStreamNonBlocking);
        cudaEventCreateWithFlags(&ef, cudaEventDisableTiming);
        cudaEventCreateWithFlags(&e1, cudaEventDisableTiming);
        cudaEventCreateWithFlags(&e2, cudaEventDisableTiming);
        cudaFuncSetAttribute(gates_gemm, cudaFuncAttributeMaxDynamicSharedMemorySize,
                             GEMM_SMEM);
        cudaFuncSetAttribute(lstm_scan, cudaFuncAttributeMaxDynamicSharedMemorySize,
                             SCAN_SMEM);
    }

    // prologue (sequential on the capture stream)
    prep<<<2048 + 65408 + 1, 128>>>(x, w_ih);
    upsample0<<<dim3(256, 128), 512>>>(z, conv0_w, conv0_b);
    upsample1<<<dim3(512, 128), 512>>>(conv1_w, conv1_b);

    // fork: gemm on s1, scan on s2 (scan consumes gx as gemm produces it)
    cudaEventRecord(ef, 0);
    cudaStreamWaitEvent(s1, ef, 0);
    cudaStreamWaitEvent(s2, ef, 0);
    gates_gemm<<<dim3(16, TST), 256, GEMM_SMEM, s1>>>(b_ih, b_hh);
    lstm_scan<<<dim3(16, 8), 256, SCAN_SMEM, s2>>>(w_hh, out);
    cudaEventRecord(e1, s1);
    cudaEventRecord(e2, s2);
    cudaStreamWaitEvent(0, e1, 0);
    cudaStreamWaitEvent(0, e2, 0);
}